// round 15
// baseline (speedup 1.0000x reference)
#include <cuda_runtime.h>
#include <math.h>
#include <stdint.h>

typedef unsigned long long u64;

#define NTW   4096
#define NUSR  2048
#define NN    6144
#define NEDGE 98304
#define SEQL  32
#define EMB   300
#define HID   100
#define BSZ   2048
#define VOCAB 50000
#define RALL  (NTW*SEQL)          /* 131072 */
#define N2D   37748736.0          /* NN*NN */
#define PWc   ((float)((37748736.0-104448.0)/104448.0))

// ---------------- f32x2 helpers ---------------------------------------------
__device__ __forceinline__ u64 bc2(float x) {
    u64 r; asm("mov.b64 %0, {%1, %1};" : "=l"(r) : "f"(x)); return r;
}
__device__ __forceinline__ void up2(u64 v, float& lo, float& hi) {
    asm("mov.b64 {%0, %1}, %2;" : "=f"(lo), "=f"(hi) : "l"(v));
}
__device__ __forceinline__ void fma2(u64& d, u64 a, u64 b) {
    asm("fma.rn.f32x2 %0, %1, %2, %0;" : "+l"(d) : "l"(a), "l"(b));
}

// ---------------- warp MMA tf32 helpers ---------------------------------------
__device__ __forceinline__ uint32_t totf32(float x) {
    uint32_t r; asm("cvt.rna.tf32.f32 %0, %1;" : "=r"(r) : "f"(x)); return r;
}
__device__ __forceinline__ void mma_tf32(float* d, const uint32_t* a,
                                         uint32_t b0, uint32_t b1) {
    asm volatile(
        "mma.sync.aligned.m16n8k8.row.col.f32.tf32.tf32.f32 "
        "{%0,%1,%2,%3}, {%4,%5,%6,%7}, {%8,%9}, {%0,%1,%2,%3};"
        : "+f"(d[0]), "+f"(d[1]), "+f"(d[2]), "+f"(d[3])
        : "r"(a[0]), "r"(a[1]), "r"(a[2]), "r"(a[3]), "r"(b0), "r"(b1));
}

// ---------------- FFMA-only special functions ---------------------------------
__device__ __forceinline__ float exp_neg(float a) {     // exp(-a), a>=0
    a = fminf(a, 80.f);
    float t = a * -1.4426950408889634f;
    float nf = floorf(t);
    float f = t - nf;
    float p = 1.3215486790144307e-06f;
    p = fmaf(p, f, 1.5252733804059841e-05f);
    p = fmaf(p, f, 1.5403530393381606e-04f);
    p = fmaf(p, f, 1.3333558146428443e-03f);
    p = fmaf(p, f, 9.6181291076284772e-03f);
    p = fmaf(p, f, 5.5504108664821580e-02f);
    p = fmaf(p, f, 2.4022650695910072e-01f);
    p = fmaf(p, f, 6.9314718055994531e-01f);
    p = fmaf(p, f, 1.0f);
    return p * __int_as_float(((int)nf + 127) << 23);
}
__device__ __forceinline__ float recip1p(float u) {     // 1/(1+u), u in [0,1]
    float D = fmaf(0.5f, u, 0.5f);
    float x = fmaf(-1.88235294f, D, 2.82352941f);
    x = fmaf(x, fmaf(-D, x, 1.f), x);
    x = fmaf(x, fmaf(-D, x, 1.f), x);
    x = fmaf(x, fmaf(-D, x, 1.f), x);
    return 0.5f * x;
}
__device__ __forceinline__ float sigmoid_ffma(float x) {
    float u = exp_neg(fabsf(x));
    float r = recip1p(u);
    return (x >= 0.f) ? r : u * r;
}

// ---------------- scratch ---------------------------------------------------
__device__ float    g_Gi [(size_t)RALL*300];
__device__ float    g_Y0 [(size_t)RALL*HID];
__device__ float    g_T1 [NUSR*100];
__device__ float    g_Xin[NN*100];
__device__ float    g_XW [NN*100];
__device__ float    g_XWc[NN*200];
__device__ float    g_Wcat[64*200];
__device__ float    g_Hc [NN*64];
__device__ float    g_Z  [NN*100];
__device__ float    g_dis[NN];
__device__ int      g_cnt[NN];
__device__ int      g_rowptr[NN+1];
__device__ int      g_fill[NN];
__device__ int      g_esrc[NEDGE];
__device__ float    g_ecoef[NEDGE];
__device__ unsigned g_Acnt [(size_t)NN*(NN/4)];
__device__ unsigned g_AcntT[(size_t)NN*(NN/4)];
__device__ double   g_accP[96];
__device__ double   g_accW[96];
__device__ double   g_accK[64];

// ---------------- warp-MMA tf32 GEMM: C[M,300] = A[M,K] @ W[300,K]^T + b -----
#define WG_SMEM ((128*36 + 304*36) * 4)

__global__ __launch_bounds__(256) void wgemm_tf32(
    const float* __restrict__ A, const float* __restrict__ W,
    const float* __restrict__ bias, float* __restrict__ C,
    int M, int K, int nchunk)
{
    extern __shared__ uint32_t wsm[];
    uint32_t* sA = wsm;             // [128][36]
    uint32_t* sB = wsm + 128*36;    // [304][36]
    int tid = threadIdx.x;
    int w = tid >> 5, lane = tid & 31;
    int g = lane >> 2, t = lane & 3;
    int m0 = blockIdx.x * 128;
    int mrow = (w & 3) * 32;
    int nbase = (w >> 2) * 152;

    float d[2][19][4];
    #pragma unroll
    for (int i = 0; i < 2; i++)
        #pragma unroll
        for (int nt = 0; nt < 19; nt++)
            #pragma unroll
            for (int q = 0; q < 4; q++) d[i][nt][q] = 0.f;

    for (int c = 0; c < nchunk; c++) {
        int kb = c * 32;
        #pragma unroll
        for (int s = 0; s < 4; s++) {
            int idx = s * 256 + tid;
            int row = idx >> 3, f4 = idx & 7;
            int k = kb + f4 * 4;
            float4 v = make_float4(0.f, 0.f, 0.f, 0.f);
            if ((m0 + row) < M && (k + 3) < K)
                v = *(const float4*)(A + (size_t)(m0 + row) * K + k);
            uint32_t* dp = &sA[row * 36 + f4 * 4];
            dp[0] = totf32(v.x); dp[1] = totf32(v.y);
            dp[2] = totf32(v.z); dp[3] = totf32(v.w);
        }
        #pragma unroll
        for (int s = 0; s < 10; s++) {
            int idx = s * 256 + tid;
            if (idx < 304 * 8) {
                int row = idx >> 3, f4 = idx & 7;
                int k = kb + f4 * 4;
                float4 v = make_float4(0.f, 0.f, 0.f, 0.f);
                if (row < 300 && (k + 3) < K)
                    v = *(const float4*)(W + (size_t)row * K + k);
                uint32_t* dp = &sB[row * 36 + f4 * 4];
                dp[0] = totf32(v.x); dp[1] = totf32(v.y);
                dp[2] = totf32(v.z); dp[3] = totf32(v.w);
            }
        }
        __syncthreads();
        #pragma unroll
        for (int ks = 0; ks < 4; ks++) {
            int k0 = ks * 8;
            uint32_t a[2][4];
            #pragma unroll
            for (int i = 0; i < 2; i++) {
                int r = mrow + i * 16 + g;
                a[i][0] = sA[r * 36 + k0 + t];
                a[i][1] = sA[(r + 8) * 36 + k0 + t];
                a[i][2] = sA[r * 36 + k0 + t + 4];
                a[i][3] = sA[(r + 8) * 36 + k0 + t + 4];
            }
            #pragma unroll
            for (int nt = 0; nt < 19; nt++) {
                int n = (nbase + nt * 8 + g) * 36 + k0;
                uint32_t b0 = sB[n + t];
                uint32_t b1 = sB[n + t + 4];
                mma_tf32(d[0][nt], a[0], b0, b1);
                mma_tf32(d[1][nt], a[1], b0, b1);
            }
        }
        __syncthreads();
    }
    #pragma unroll
    for (int i = 0; i < 2; i++) {
        int r1 = m0 + mrow + i * 16 + g;
        int r2 = r1 + 8;
        #pragma unroll
        for (int nt = 0; nt < 19; nt++) {
            int col = nbase + nt * 8 + 2 * t;
            if (col >= 300) continue;
            float b0 = bias[col], b1 = bias[col + 1];
            if (r1 < M) {
                C[(size_t)r1 * 300 + col]     = d[i][nt][0] + b0;
                C[(size_t)r1 * 300 + col + 1] = d[i][nt][1] + b1;
            }
            if (r2 < M) {
                C[(size_t)r2 * 300 + col]     = d[i][nt][2] + b0;
                C[(size_t)r2 * 300 + col + 1] = d[i][nt][3] + b1;
            }
        }
    }
}

// ---------------- SGEMM v4 (SIMT, small GEMMs) --------------------------------
template<int BT, int QN>
__global__ __launch_bounds__(256) void sgemm4(
    const float* __restrict__ A, const float* __restrict__ B,
    const float* __restrict__ bias, float* __restrict__ C,
    int M, int N, int K, int act, int n0base)
{
    __shared__ __align__(16) float As[16][132];
    __shared__ __align__(16) float Bs[16][212];
    int tid = threadIdx.x;
    int m0 = blockIdx.y * 128;
    int n0 = blockIdx.x * (QN * 16) + n0base;

    int ra = tid >> 1, ka = (tid & 1) * 8;
    int gmA = m0 + ra;
    bool rokA = gmA < M;
    const float* Arow = A + (size_t)(rokA ? gmA : 0) * K;
    bool kal = ((K & 3) == 0);

    int rb, kb;
    const float* Brow = nullptr;
    bool rokB = true;
    if (BT) {
        rb = tid >> 1; kb = (tid & 1) * 8;
        rokB = (rb < QN * 16) && (n0 + rb) < N;
        Brow = B + (size_t)(rokB ? (n0 + rb) : 0) * K;
    } else {
        rb = tid >> 4; kb = (tid & 15) * 16;   // up to 16 cols per loader thread
    }

    float4 rA0, rA1;
    float rBv[16];

    auto fetch = [&](int k0) {
        rA0 = make_float4(0.f,0.f,0.f,0.f); rA1 = rA0;
        if (rokA) {
            int k = k0 + ka;
            if (kal && (k + 7) < K) {
                rA0 = *(const float4*)(Arow + k);
                rA1 = *(const float4*)(Arow + k + 4);
            } else {
                float t[8];
                #pragma unroll
                for (int i = 0; i < 8; i++) t[i] = ((k+i) < K) ? Arow[k+i] : 0.f;
                rA0 = make_float4(t[0],t[1],t[2],t[3]);
                rA1 = make_float4(t[4],t[5],t[6],t[7]);
            }
        }
        if (BT) {
            if (rokB) {
                int k = k0 + kb;
                #pragma unroll
                for (int i = 0; i < 8; i++)
                    rBv[i] = ((k+i) < K) ? Brow[k+i] : 0.f;
            } else {
                #pragma unroll
                for (int i = 0; i < 8; i++) rBv[i] = 0.f;
            }
        } else {
            int kk = k0 + rb;
            #pragma unroll
            for (int i = 0; i < 16; i++) {
                int col = n0 + kb + i;
                rBv[i] = (kk < K && kb + i < QN*16 && col < N)
                         ? B[(size_t)kk * N + col] : 0.f;
            }
        }
    };
    auto stage = [&]() {
        As[ka+0][ra]=rA0.x; As[ka+1][ra]=rA0.y; As[ka+2][ra]=rA0.z; As[ka+3][ra]=rA0.w;
        As[ka+4][ra]=rA1.x; As[ka+5][ra]=rA1.y; As[ka+6][ra]=rA1.z; As[ka+7][ra]=rA1.w;
        if (BT) {
            if (rb < QN*16) {
                #pragma unroll
                for (int i = 0; i < 8; i++) Bs[kb+i][rb] = rBv[i];
            }
        } else {
            #pragma unroll
            for (int i = 0; i < 16; i++)
                if (kb + i < QN*16) Bs[rb][kb+i] = rBv[i];
        }
    };

    u64 acc[4][QN];
    #pragma unroll
    for (int p = 0; p < 4; p++)
        #pragma unroll
        for (int q = 0; q < QN; q++) acc[p][q] = 0ull;

    int ty = tid >> 4, tx = tid & 15;
    int i0 = ty * 8;
    int T = (K + 15) / 16;
    fetch(0);
    for (int t = 0; t < T; t++) {
        stage();
        __syncthreads();
        if (t + 1 < T) fetch((t + 1) * 16);
        #pragma unroll
        for (int k = 0; k < 16; k++) {
            u64 a2[4];
            #pragma unroll
            for (int p = 0; p < 4; p++)
                a2[p] = *(const u64*)&As[k][i0 + 2*p];
            #pragma unroll
            for (int q = 0; q < QN; q++) {
                u64 bb = bc2(Bs[k][q*16 + tx]);
                #pragma unroll
                for (int p = 0; p < 4; p++) fma2(acc[p][q], a2[p], bb);
            }
        }
        __syncthreads();
    }

    #pragma unroll
    for (int p = 0; p < 4; p++) {
        int m1 = m0 + i0 + 2*p, m2 = m1 + 1;
        #pragma unroll
        for (int q = 0; q < QN; q++) {
            int n = n0 + q*16 + tx;
            if (n >= N) continue;
            float lo, hi; up2(acc[p][q], lo, hi);
            if (m1 < M) {
                float v = lo; if (bias) v += bias[n];
                if (act == 1) v = fmaxf(v, 0.f);
                C[(size_t)m1*N+n] = v;
            }
            if (m2 < M) {
                float v = hi; if (bias) v += bias[n];
                if (act == 1) v = fmaxf(v, 0.f);
                C[(size_t)m2*N+n] = v;
            }
        }
    }
}

// ---------------- persistent GRU layer (tensor GEMM + balanced gates) --------
#define GRU_SMEM (53384*4)

template<int LAYER>
__global__ __launch_bounds__(256) void gru_persist(
    const float* __restrict__ GIsrc,
    const int*   __restrict__ gnf,
    const float* __restrict__ whh, const float* __restrict__ bhh,
    const float* __restrict__ h0,
    float* __restrict__ Yout)
{
    extern __shared__ float sm[];
    uint32_t* sWt  = (uint32_t*)sm;            // [320][108]
    uint32_t* sHta = (uint32_t*)(sm + 34560);  // [32][108]
    float* sG  = sm + 38016;                   // [32][332]
    float* sHT = sm + 48640;                   // [100][34]
    float* sB  = sm + 52040;                   // [320]
    int*  sTok = (int*)(sm + 52360);           // [1024]
    int tid = threadIdx.x;
    int w = tid >> 5, lane = tid & 31;
    int g = lane >> 2, t = lane & 3;
    int w5 = w * 5;
    int rowbase = blockIdx.x * 32;

    for (int idx = tid; idx < 320 * 108; idx += 256) {
        int col = idx / 108, k = idx - col * 108;
        float v = (col < 300 && k < 100) ? whh[col * 100 + k] : 0.f;
        sWt[idx] = totf32(v);
    }
    for (int idx = tid; idx < 32 * 108; idx += 256) {
        int r = idx / 108, k = idx - r * 108;
        float v = (k < 100) ? h0[(size_t)(rowbase + r) * 100 + k] : 0.f;
        sHta[idx] = totf32(v);
    }
    for (int idx = tid; idx < 3200; idx += 256) {
        int r = idx / 100, c = idx - r * 100;
        sHT[c*34 + r] = h0[(size_t)(rowbase + r)*100 + c];
    }
    for (int idx = tid; idx < 320; idx += 256) sB[idx] = (idx < 300) ? bhh[idx] : 0.f;
    if (LAYER == 0) {
        for (int idx = tid; idx < 1024; idx += 256)
            sTok[idx] = gnf[rowbase * SEQL + idx];
    }
    __syncthreads();

    int pr[13], pc[13];
    #pragma unroll
    for (int q = 0; q < 13; q++) {
        int cell = tid + q * 256;
        pr[q] = cell / 100;
        pc[q] = cell - pr[q] * 100;
    }

    for (int s = 0; s < SEQL; s++) {
        float pg[13][3];
        #pragma unroll
        for (int q = 0; q < 13; q++) {
            int cell = tid + q * 256;
            if (cell < 3200) {
                int r = pr[q], c = pc[q];
                const float* gi;
                if (LAYER == 0) {
                    int tok = sTok[r * SEQL + s];
                    gi = GIsrc + (size_t)tok * 300;
                } else {
                    gi = GIsrc + ((size_t)s * NTW + (rowbase + r)) * 300;
                }
                pg[q][0] = gi[c];
                pg[q][1] = gi[c + 100];
                pg[q][2] = gi[c + 200];
            }
        }

        float dfr[2][5][4];
        #pragma unroll
        for (int i = 0; i < 2; i++)
            #pragma unroll
            for (int j = 0; j < 5; j++)
                #pragma unroll
                for (int q = 0; q < 4; q++) dfr[i][j][q] = 0.f;

        #pragma unroll
        for (int ks = 0; ks < 13; ks++) {
            int k0 = ks * 8;
            uint32_t a[2][4];
            #pragma unroll
            for (int i = 0; i < 2; i++) {
                int r = i * 16 + g;
                a[i][0] = sHta[r * 108 + k0 + t];
                a[i][1] = sHta[(r + 8) * 108 + k0 + t];
                a[i][2] = sHta[r * 108 + k0 + t + 4];
                a[i][3] = sHta[(r + 8) * 108 + k0 + t + 4];
            }
            #pragma unroll
            for (int j = 0; j < 5; j++) {
                int cb = (w5 + j) * 8 + g;
                uint32_t b0 = sWt[cb * 108 + k0 + t];
                uint32_t b1 = sWt[cb * 108 + k0 + t + 4];
                mma_tf32(dfr[0][j], a[0], b0, b1);
                mma_tf32(dfr[1][j], a[1], b0, b1);
            }
        }
        #pragma unroll
        for (int i = 0; i < 2; i++) {
            int r1 = i * 16 + g, r2 = r1 + 8;
            #pragma unroll
            for (int j = 0; j < 5; j++) {
                int col = (w5 + j) * 8 + 2 * t;
                sG[r1 * 332 + col]     = dfr[i][j][0];
                sG[r1 * 332 + col + 1] = dfr[i][j][1];
                sG[r2 * 332 + col]     = dfr[i][j][2];
                sG[r2 * 332 + col + 1] = dfr[i][j][3];
            }
        }
        __syncthreads();

        // gates: rg on FFMA; zg + tanh on MUFU (pipe balance)
        #pragma unroll
        for (int q = 0; q < 13; q++) {
            int cell = tid + q * 256;
            if (cell < 3200) {
                int r = pr[q], c = pc[q];
                float hr  = sG[r*332 + c]       + sB[c];
                float hz  = sG[r*332 + c + 100] + sB[c+100];
                float hnn = sG[r*332 + c + 200] + sB[c+200];
                float h   = sHT[c*34 + r];
                float rg = sigmoid_ffma(pg[q][0] + hr);
                float zg = __fdividef(1.f, 1.f + __expf(-(pg[q][1] + hz)));
                float x  = pg[q][2] + rg * hnn;
                float tt = __expf(-2.f * fabsf(x));
                float ng = copysignf(__fdividef(1.f - tt, 1.f + tt), x);
                float hn = (1.f - zg) * ng + zg * h;
                sHT[c*34 + r] = hn;
                sHta[r*108 + c] = totf32(hn);
                if (LAYER == 0)
                    Yout[((size_t)s * NTW + (rowbase + r)) * 100 + c] = hn;
            }
        }
        __syncthreads();
    }
    if (LAYER == 1) {
        for (int ii = tid; ii < 3200; ii += 256) {
            int r = ii / 100, c = ii - r * 100;
            int grow = rowbase + r;
            int orow = (grow < BSZ) ? grow : grow + NUSR;
            Yout[(size_t)orow * 100 + c] = sHT[c*34 + r];
        }
    }
}

// ---------------- graph structure kernels ------------------------------------
__global__ void k_zero3(double* accP, double* accW, double* accK) {
    int i = threadIdx.x;
    if (i < 96) { accP[i] = 0.0; accW[i] = 0.0; }
    if (i < 64) accK[i] = 0.0;
}
__global__ void k_cat(const float* __restrict__ cmw, const float* __restrict__ clw,
                      float* __restrict__ wcat) {
    int i = blockIdx.x * 256 + threadIdx.x;
    if (i >= 64 * 200) return;
    int k = i / 200, c = i - k * 200;
    wcat[i] = (c < 100) ? cmw[k * 100 + c] : clw[k * 100 + (c - 100)];
}
__global__ void k_scatter_cnt(const int* __restrict__ src, const int* __restrict__ dst,
                              unsigned* __restrict__ cnt, unsigned* __restrict__ cntT,
                              int* __restrict__ deg) {
    int e = blockIdx.x * 256 + threadIdx.x;
    if (e >= NEDGE) return;
    int s = src[e], d = dst[e];
    size_t idx  = (size_t)s * NN + d;
    size_t idxT = (size_t)d * NN + s;
    atomicAdd(&cnt [idx  >> 2], 1u << ((idx  & 3) * 8));
    atomicAdd(&cntT[idxT >> 2], 1u << ((idxT & 3) * 8));
    atomicAdd(&deg[d], 1);
}
__global__ __launch_bounds__(1024) void k_prefix(const int* __restrict__ cnt,
                                                 int* __restrict__ rowptr,
                                                 int* __restrict__ fill,
                                                 float* __restrict__ dis) {
    __shared__ int part[1024];
    int tid = threadIdx.x;
    int base = tid * 6;
    int loc[6], cv[6];
    int s = 0;
    #pragma unroll
    for (int i = 0; i < 6; i++) { cv[i] = cnt[base + i]; loc[i] = s; s += cv[i]; }
    part[tid] = s;
    __syncthreads();
    for (int o = 1; o < 1024; o <<= 1) {
        int t = (tid >= o) ? part[tid - o] : 0;
        __syncthreads();
        part[tid] += t;
        __syncthreads();
    }
    int excl = part[tid] - s;
    #pragma unroll
    for (int i = 0; i < 6; i++) {
        rowptr[base + i] = excl + loc[i];
        fill[base + i] = 0;
        dis[base + i] = rsqrtf((float)cv[i] + 1.f);
    }
    if (tid == 1023) rowptr[NN] = part[1023];
}
__global__ void k_fill(const int* __restrict__ src, const int* __restrict__ dst,
                       const int* __restrict__ rowptr, int* __restrict__ fill,
                       const float* __restrict__ dis,
                       int* __restrict__ esrc, float* __restrict__ ecoef) {
    int e = blockIdx.x * 256 + threadIdx.x;
    if (e >= NEDGE) return;
    int s = src[e], d = dst[e];
    int pos = rowptr[d] + atomicAdd(&fill[d], 1);
    esrc[pos] = s;
    ecoef[pos] = dis[s] * dis[d];
}

// ---------------- CSR aggregation kernels -------------------------------------
__global__ __launch_bounds__(256) void k_agg1(
    const float* __restrict__ xw, const float* __restrict__ b,
    const int* __restrict__ rowptr, const int* __restrict__ esrc,
    const float* __restrict__ ecoef, const float* __restrict__ dis,
    float* __restrict__ outv)
{
    int task = blockIdx.x * 8 + (threadIdx.x >> 5);
    int lane = threadIdx.x & 31;
    int n = task >> 1;
    int c = ((task & 1) << 5) + lane;
    if (n >= NN) return;
    float dn = dis[n];
    float v = xw[(size_t)n*64 + c] * dn * dn + b[c];
    int p1 = rowptr[n+1];
    for (int p = rowptr[n]; p < p1; p++) {
        int s = esrc[p];
        v = fmaf(xw[(size_t)s*64 + c], ecoef[p], v);
    }
    outv[(size_t)n*64 + c] = (v > 0.f) ? v : expm1f(v);
}
__global__ __launch_bounds__(256) void k_aggmulv(
    const float* __restrict__ xwc,
    const float* __restrict__ bm, const float* __restrict__ bl,
    const int* __restrict__ rowptr, const int* __restrict__ esrc,
    const float* __restrict__ ecoef, const float* __restrict__ dis,
    const float* __restrict__ eps, float* __restrict__ Z,
    float* __restrict__ out, double* __restrict__ accK)
{
    __shared__ float wred[8];
    int task = blockIdx.x * 8 + (threadIdx.x >> 5);
    int lane = threadIdx.x & 31;
    int n = task >> 2;
    int c = ((task & 3) << 5) + lane;
    float kl = 0.f;
    if (n < NN && c < 100) {
        float dn = dis[n];
        float d2 = dn * dn;
        float vm = fmaf(xwc[(size_t)n*200 + c],       d2, bm[c]);
        float vl = fmaf(xwc[(size_t)n*200 + 100 + c], d2, bl[c]);
        int p1 = rowptr[n+1];
        for (int p = rowptr[n]; p < p1; p++) {
            int s = esrc[p];
            float co = ecoef[p];
            vm = fmaf(xwc[(size_t)s*200 + c],       co, vm);
            vl = fmaf(xwc[(size_t)s*200 + 100 + c], co, vl);
        }
        float mu = fmaxf(vm, 0.f);
        float lv = fmaxf(vl, 0.f);
        float z = fmaf(expf(lv * 0.5f), eps[(size_t)n*100 + c], mu);
        Z[(size_t)n*100 + c] = z;
        if (n < BSZ) out[(size_t)n*100 + c] = z;
        kl = -0.5f * (1.f + lv - mu*mu - expf(lv));
    }
    #pragma unroll
    for (int o = 16; o > 0; o >>= 1)
        kl += __shfl_down_sync(0xFFFFFFFFu, kl, o);
    if (lane == 0) wred[threadIdx.x >> 5] = kl;
    __syncthreads();
    if (threadIdx.x == 0) {
        float t = 0.f;
        #pragma unroll
        for (int w = 0; w < 8; w++) t += wred[w];
        atomicAdd(&accK[blockIdx.x & 63], (double)t);
    }
}

// ---------------- Z@Z^T loss: tensor dot + reduced-MUFU epilogue --------------
#define ZZT_SMEM (2*64*108*4)
__global__ __launch_bounds__(256) void k_zzt7(const float* __restrict__ Z,
                                              const unsigned* __restrict__ cnt,
                                              const unsigned* __restrict__ cntT,
                                              double* __restrict__ accP,
                                              double* __restrict__ accW) {
    int q = blockIdx.x;
    int bjB = (int)((sqrt(8.0 * q + 1.0) - 1.0) * 0.5);
    while ((bjB + 1) * (bjB + 2) / 2 <= q) bjB++;
    while (bjB * (bjB + 1) / 2 > q) bjB--;
    int biB = q - bjB * (bjB + 1) / 2;

    extern __shared__ uint32_t zsm[];
    uint32_t* zA = zsm;             // [64][108] tf32
    uint32_t* zB = zsm + 64*108;    // [64][108] tf32
    int tid = threadIdx.x;
    int w = tid >> 5, lane = tid & 31;
    int g = lane >> 2, t = lane & 3;
    int bi = biB * 64, bj = bjB * 64;

    for (int f = tid; f < 64 * 104; f += 256) {
        int r = f / 104, k = f - r * 104;
        float va = (k < 100) ? Z[(size_t)(bi + r) * 100 + k] : 0.f;
        float vb = (k < 100) ? Z[(size_t)(bj + r) * 100 + k] : 0.f;
        zA[r * 108 + k] = totf32(va);
        zB[r * 108 + k] = totf32(vb);
    }
    __syncthreads();

    int mg = (w & 1) * 32;
    int ngrp = (w >> 1) * 16;

    float d[2][2][4];
    #pragma unroll
    for (int i = 0; i < 2; i++)
        #pragma unroll
        for (int j = 0; j < 2; j++)
            #pragma unroll
            for (int e = 0; e < 4; e++) d[i][j][e] = 0.f;

    #pragma unroll
    for (int ks = 0; ks < 13; ks++) {
        int k0 = ks * 8;
        uint32_t a[2][4];
        #pragma unroll
        for (int i = 0; i < 2; i++) {
            int r = mg + i * 16 + g;
            a[i][0] = zA[r * 108 + k0 + t];
            a[i][1] = zA[(r + 8) * 108 + k0 + t];
            a[i][2] = zA[r * 108 + k0 + t + 4];
            a[i][3] = zA[(r + 8) * 108 + k0 + t + 4];
        }
        #pragma unroll
        for (int j = 0; j < 2; j++) {
            int cb = ngrp + j * 8 + g;
            uint32_t b0 = zB[cb * 108 + k0 + t];
            uint32_t b1 = zB[cb * 108 + k0 + t + 4];
            mma_tf32(d[0][j], a[0], b0, b1);
            mma_tf32(d[1][j], a[1], b0, b1);
        }
    }

    bool diag = (biB == bjB);
    float sp = 0.f, sw = 0.f;
    #pragma unroll
    for (int i = 0; i < 2; i++) {
        #pragma unroll
        for (int half = 0; half < 2; half++) {
            int iloc = mg + i * 16 + g + half * 8;
            int ig = bi + iloc;
            #pragma unroll
            for (int j = 0; j < 2; j++) {
                int cloc = ngrp + j * 8 + 2 * t;
                int jg = bj + cloc;
                unsigned wrow  = cnt [(size_t)ig * (NN/4) + ((unsigned)jg >> 2)];
                unsigned wrowT = diag ? 0u
                               : cntT[(size_t)ig * (NN/4) + ((unsigned)jg >> 2)];
                #pragma unroll
                for (int e = 0; e < 2; e++) {
                    float zv = d[i][j][half * 2 + e];
                    int col = jg + e;
                    // reduced-MUFU: 1 exp + 1 log per cell
                    float u = __expf(-fabsf(zv));        // MUFU 1
                    float r = recip1p(u);                // FFMA
                    float s = (zv >= 0.f) ? r : u * r;
                    float lg = __logf(1.f + u);          // MUFU 2
                    float mlogp, mlog1mp;
                    if (zv > 15.942384f) {
                        mlogp = 1.1920929e-7f; mlog1mp = 15.9423847f;
                    } else if (zv < -16.118095f) {
                        mlogp = 16.118095f;    mlog1mp = 1.0000000e-7f;
                    } else {
                        mlogp = (zv >= 0.f) ? lg : (lg - zv);  // softplus(-z)
                        mlog1mp = zv + mlogp;
                    }
                    float ag1 = (float)((wrow >> ((col & 3) * 8)) & 0xFFu)
                              + ((ig == col) ? 1.f : 0.f);
                    float wg1 = (ag1 == 1.f) ? PWc : 1.f;
                    sp += s;
                    sw += wg1 * (ag1 * mlogp + (1.f - ag1) * mlog1mp);
                    if (!diag) {
                        float ag2 = (float)((wrowT >> ((col & 3) * 8)) & 0xFFu);
                        float wg2 = (ag2 == 1.f) ? PWc : 1.f;
                        sp += s;
                        sw += wg2 * (ag2 * mlogp + (1.f - ag2) * mlog1mp);
                    }
                }
            }
        }
    }
    __syncthreads();
    double* red = (double*)zsm;
    red[tid] = (double)sp; __syncthreads();
    for (int o = 128; o > 0; o >>= 1) {
        if (tid < o) red[tid] += red[tid + o];
        __syncthreads();
    }
    if (tid == 0) atomicAdd(&accP[bjB], red[0]);
    __syncthreads();
    red[tid] = (double)sw; __syncthreads();
    for (int o = 128; o > 0; o >>= 1) {
        if (tid < o) red[tid] += red[tid + o];
        __syncthreads();
    }
    if (tid == 0) atomicAdd(&accW[bjB], red[0]);
}

__global__ void k_fin(const double* __restrict__ accP, const double* __restrict__ accW,
                      const double* __restrict__ accK, float* __restrict__ out) {
    double sp = 0.0, sw = 0.0, sk = 0.0;
    for (int i = 0; i < 96; i++) { sp += accP[i]; sw += accW[i]; }
    for (int i = 0; i < 64; i++) sk += accK[i];
    double norm = N2D / ((N2D - sp) * 2.0);
    out[BSZ * 100]     = (float)(sk / (double)NN);
    out[BSZ * 100 + 1] = (float)(norm * (sw / N2D));
}

// ---------------- host launch ------------------------------------------------
extern "C" void kernel_launch(void* const* d_in, const int* in_sizes, int n_in,
                              void* d_out, int out_size) {
    const float* user_feats = (const float*)d_in[0];
    const int*   gnf        = (const int*)  d_in[1];
    const int*   eidx       = (const int*)  d_in[2];
    const float* h0         = (const float*)d_in[4];
    const float* eps        = (const float*)d_in[5];
    const float* emb        = (const float*)d_in[6];
    const float* mw1 = (const float*)d_in[7],  *mb1 = (const float*)d_in[8];
    const float* mw2 = (const float*)d_in[9],  *mb2 = (const float*)d_in[10];
    const float* wih0 = (const float*)d_in[11], *whh0 = (const float*)d_in[12];
    const float* bih0 = (const float*)d_in[13], *bhh0 = (const float*)d_in[14];
    const float* wih1 = (const float*)d_in[15], *whh1 = (const float*)d_in[16];
    const float* bih1 = (const float*)d_in[17], *bhh1 = (const float*)d_in[18];
    const float* c1w = (const float*)d_in[19], *c1b = (const float*)d_in[20];
    const float* cmw = (const float*)d_in[21], *cmb = (const float*)d_in[22];
    const float* clw = (const float*)d_in[23], *clb = (const float*)d_in[24];
    float* out = (float*)d_out;
    const int* srcp = eidx;
    const int* dstp = eidx + NEDGE;

    void* p;
    cudaGetSymbolAddress(&p, g_Gi);  float* Gi  = (float*)p;
    cudaGetSymbolAddress(&p, g_Y0);  float* Y0  = (float*)p;
    cudaGetSymbolAddress(&p, g_T1);  float* T1  = (float*)p;
    cudaGetSymbolAddress(&p, g_Xin); float* Xin = (float*)p;
    cudaGetSymbolAddress(&p, g_XW);  float* XW1 = (float*)p;
    cudaGetSymbolAddress(&p, g_XWc); float* XWc = (float*)p;
    cudaGetSymbolAddress(&p, g_Wcat); float* Wcat = (float*)p;
    cudaGetSymbolAddress(&p, g_Hc);  float* Hc  = (float*)p;
    cudaGetSymbolAddress(&p, g_Z);   float* Z   = (float*)p;
    cudaGetSymbolAddress(&p, g_dis); float* dis = (float*)p;
    cudaGetSymbolAddress(&p, g_cnt);    int* cntI = (int*)p;
    cudaGetSymbolAddress(&p, g_rowptr); int* rowptr = (int*)p;
    cudaGetSymbolAddress(&p, g_fill);   int* fill = (int*)p;
    cudaGetSymbolAddress(&p, g_esrc);   int* esrc = (int*)p;
    cudaGetSymbolAddress(&p, g_ecoef);  float* ecoef = (float*)p;
    cudaGetSymbolAddress(&p, g_Acnt);   unsigned* Acnt = (unsigned*)p;
    cudaGetSymbolAddress(&p, g_AcntT);  unsigned* AcntT = (unsigned*)p;
    cudaGetSymbolAddress(&p, g_accP);   double* accP = (double*)p;
    cudaGetSymbolAddress(&p, g_accW);   double* accW = (double*)p;
    cudaGetSymbolAddress(&p, g_accK);   double* accK = (double*)p;

    static bool inited = false;
    static cudaStream_t s2;
    static cudaEvent_t evRoot, evSetup;
    if (!inited) {
        cudaStreamCreateWithFlags(&s2, cudaStreamNonBlocking);
        cudaEventCreateWithFlags(&evRoot,  cudaEventDisableTiming);
        cudaEventCreateWithFlags(&evSetup, cudaEventDisableTiming);
        cudaFuncSetAttribute(gru_persist<0>, cudaFuncAttributeMaxDynamicSharedMemorySize, GRU_SMEM);
        cudaFuncSetAttribute(gru_persist<1>, cudaFuncAttributeMaxDynamicSharedMemorySize, GRU_SMEM);
        cudaFuncSetAttribute(k_zzt7, cudaFuncAttributeMaxDynamicSharedMemorySize, ZZT_SMEM);
        cudaFuncSetAttribute(wgemm_tf32, cudaFuncAttributeMaxDynamicSharedMemorySize, WG_SMEM);
        inited = true;
    }

    cudaEventRecord(evRoot, 0);

    // ---- side stream s2: graph setup + user MLP + weight concat ----
    cudaStreamWaitEvent(s2, evRoot, 0);
    cudaMemsetAsync(Acnt,  0, (size_t)NN * (NN/4) * sizeof(unsigned), s2);
    cudaMemsetAsync(AcntT, 0, (size_t)NN * (NN/4) * sizeof(unsigned), s2);
    cudaMemsetAsync(cntI, 0, NN * sizeof(int), s2);
    k_zero3<<<1, 128, 0, s2>>>(accP, accW, accK);
    k_cat<<<50, 256, 0, s2>>>(cmw, clw, Wcat);
    k_scatter_cnt<<<(NEDGE + 255)/256, 256, 0, s2>>>(srcp, dstp, Acnt, AcntT, cntI);
    k_prefix<<<1, 1024, 0, s2>>>(cntI, rowptr, fill, dis);
    k_fill<<<(NEDGE + 255)/256, 256, 0, s2>>>(srcp, dstp, rowptr, fill, dis, esrc, ecoef);
    sgemm4<0,7><<<dim3(1, 16), 256, 0, s2>>>(user_feats, mw1, mb1, T1, NUSR, 100, 9, 1, 0);
    sgemm4<0,7><<<dim3(1, 16), 256, 0, s2>>>(T1, mw2, mb2, Xin + (size_t)BSZ*100, NUSR, 100, 100, 0, 0);
    cudaEventRecord(evSetup, s2);

    // ---- main: E2G (warp-MMA tf32) ----
    wgemm_tf32<<<(VOCAB + 127)/128, 256, WG_SMEM>>>(emb, wih0, bih0, Gi, VOCAB, 300, 10);

    gru_persist<0><<<128, 256, GRU_SMEM>>>(Gi, gnf, whh0, bhh0, h0, Y0);

    // ---- Gi1 (warp-MMA tf32) ----
    wgemm_tf32<<<RALL/128, 256, WG_SMEM>>>(Y0, wih1, bih1, Gi, RALL, 100, 4);

    gru_persist<1><<<128, 256, GRU_SMEM>>>(Gi, nullptr, whh1, bhh1,
                                           h0 + (size_t)NTW*HID, Xin);

    // join setup (CSR + UE rows of Xin + Wcat) before convs
    cudaStreamWaitEvent(0, evSetup, 0);

    // conv1 -> elu
    sgemm4<0,4><<<dim3(1, 48), 256>>>(Xin, c1w, nullptr, XW1, NN, 64, 100, 0, 0);
    k_agg1<<<NN*2/8, 256>>>(XW1, c1b, rowptr, esrc, ecoef, dis, Hc);

    // convmu + convlv in one GEMM (N=200 concat)
    sgemm4<0,13><<<dim3(1, 48), 256>>>(Hc, Wcat, nullptr, XWc, NN, 200, 64, 0, 0);

    k_aggmulv<<<NN*4/8, 256>>>(XWc, cmb, clb, rowptr, esrc, ecoef, dis,
                               eps, Z, out, accK);

    k_zzt7<<<96*97/2, 256, ZZT_SMEM>>>(Z, Acnt, AcntT, accP, accW);
    k_fin<<<1, 1>>>(accP, accW, accK, out);
}

// round 16
// speedup vs baseline: 1.0731x; 1.0731x over previous
#include <cuda_runtime.h>
#include <cuda_bf16.h>
#include <math.h>
#include <stdint.h>

typedef unsigned long long u64;

#define NTW   4096
#define NUSR  2048
#define NN    6144
#define NEDGE 98304
#define SEQL  32
#define EMB   300
#define HID   100
#define BSZ   2048
#define VOCAB 50000
#define RALL  (NTW*SEQL)          /* 131072 */
#define N2D   37748736.0          /* NN*NN */
#define PWc   ((float)((37748736.0-104448.0)/104448.0))

// ---------------- f32x2 helpers ---------------------------------------------
__device__ __forceinline__ u64 bc2(float x) {
    u64 r; asm("mov.b64 %0, {%1, %1};" : "=l"(r) : "f"(x)); return r;
}
__device__ __forceinline__ void up2(u64 v, float& lo, float& hi) {
    asm("mov.b64 {%0, %1}, %2;" : "=f"(lo), "=f"(hi) : "l"(v));
}
__device__ __forceinline__ void fma2(u64& d, u64 a, u64 b) {
    asm("fma.rn.f32x2 %0, %1, %2, %0;" : "+l"(d) : "l"(a), "l"(b));
}

// ---------------- warp MMA tf32 helpers ---------------------------------------
__device__ __forceinline__ uint32_t totf32(float x) {
    uint32_t r; asm("cvt.rna.tf32.f32 %0, %1;" : "=r"(r) : "f"(x)); return r;
}
__device__ __forceinline__ void mma_tf32(float* d, const uint32_t* a,
                                         uint32_t b0, uint32_t b1) {
    asm volatile(
        "mma.sync.aligned.m16n8k8.row.col.f32.tf32.tf32.f32 "
        "{%0,%1,%2,%3}, {%4,%5,%6,%7}, {%8,%9}, {%0,%1,%2,%3};"
        : "+f"(d[0]), "+f"(d[1]), "+f"(d[2]), "+f"(d[3])
        : "r"(a[0]), "r"(a[1]), "r"(a[2]), "r"(a[3]), "r"(b0), "r"(b1));
}

// ---------------- FFMA-only special functions ---------------------------------
__device__ __forceinline__ float exp_neg(float a) {
    a = fminf(a, 80.f);
    float t = a * -1.4426950408889634f;
    float nf = floorf(t);
    float f = t - nf;
    float p = 1.3215486790144307e-06f;
    p = fmaf(p, f, 1.5252733804059841e-05f);
    p = fmaf(p, f, 1.5403530393381606e-04f);
    p = fmaf(p, f, 1.3333558146428443e-03f);
    p = fmaf(p, f, 9.6181291076284772e-03f);
    p = fmaf(p, f, 5.5504108664821580e-02f);
    p = fmaf(p, f, 2.4022650695910072e-01f);
    p = fmaf(p, f, 6.9314718055994531e-01f);
    p = fmaf(p, f, 1.0f);
    return p * __int_as_float(((int)nf + 127) << 23);
}
__device__ __forceinline__ float recip1p(float u) {
    float D = fmaf(0.5f, u, 0.5f);
    float x = fmaf(-1.88235294f, D, 2.82352941f);
    x = fmaf(x, fmaf(-D, x, 1.f), x);
    x = fmaf(x, fmaf(-D, x, 1.f), x);
    x = fmaf(x, fmaf(-D, x, 1.f), x);
    return 0.5f * x;
}
__device__ __forceinline__ float sigmoid_ffma(float x) {
    float u = exp_neg(fabsf(x));
    float r = recip1p(u);
    return (x >= 0.f) ? r : u * r;
}

// ---------------- scratch ---------------------------------------------------
__device__ __nv_bfloat16 g_Gi [(size_t)RALL*300];   // bf16 gate preacts
__device__ __nv_bfloat16 g_Y0 [(size_t)RALL*HID];   // bf16 layer-0 outputs
__device__ float    g_T1 [NUSR*100];
__device__ float    g_Xin[NN*100];
__device__ float    g_XW [NN*100];
__device__ float    g_XWc[NN*200];
__device__ float    g_Wcat[64*200];
__device__ float    g_Hc [NN*64];
__device__ float    g_Z  [NN*100];
__device__ float    g_dis[NN];
__device__ int      g_cnt[NN];
__device__ int      g_rowptr[NN+1];
__device__ int      g_fill[NN];
__device__ int      g_esrc[NEDGE];
__device__ float    g_ecoef[NEDGE];
__device__ unsigned g_Acnt [(size_t)NN*(NN/4)];
__device__ unsigned g_AcntT[(size_t)NN*(NN/4)];
__device__ double   g_accP[96];
__device__ double   g_accW[96];
__device__ double   g_accK[64];

// ---------------- warp-MMA tf32 GEMM -> bf16 out ------------------------------
// C[M,300](bf16) = A[M,K] @ W[300,K]^T + b.  ABF: A is bf16 (lossless->tf32).
#define WG_SMEM ((128*36 + 304*36) * 4)

template<int ABF>
__global__ __launch_bounds__(256) void wgemm_tf32(
    const void* __restrict__ Araw, const float* __restrict__ W,
    const float* __restrict__ bias, __nv_bfloat16* __restrict__ C,
    int M, int K, int nchunk)
{
    extern __shared__ uint32_t wsm[];
    uint32_t* sA = wsm;             // [128][36]
    uint32_t* sB = wsm + 128*36;    // [304][36]
    int tid = threadIdx.x;
    int w = tid >> 5, lane = tid & 31;
    int g = lane >> 2, t = lane & 3;
    int m0 = blockIdx.x * 128;
    int mrow = (w & 3) * 32;
    int nbase = (w >> 2) * 152;

    float d[2][19][4];
    #pragma unroll
    for (int i = 0; i < 2; i++)
        #pragma unroll
        for (int nt = 0; nt < 19; nt++)
            #pragma unroll
            for (int q = 0; q < 4; q++) d[i][nt][q] = 0.f;

    for (int c = 0; c < nchunk; c++) {
        int kb = c * 32;
        #pragma unroll
        for (int s = 0; s < 4; s++) {
            int idx = s * 256 + tid;
            int row = idx >> 3, f4 = idx & 7;
            int k = kb + f4 * 4;
            uint32_t* dp = &sA[row * 36 + f4 * 4];
            bool rok = (m0 + row) < M;
            if (ABF) {
                const __nv_bfloat16* Ar = (const __nv_bfloat16*)Araw
                                        + (size_t)(rok ? (m0 + row) : 0) * K;
                if (rok && (k + 3) < K) {
                    uint2 u = *(const uint2*)(Ar + k);
                    dp[0] = (u.x & 0xFFFFu) << 16; dp[1] = u.x & 0xFFFF0000u;
                    dp[2] = (u.y & 0xFFFFu) << 16; dp[3] = u.y & 0xFFFF0000u;
                } else {
                    #pragma unroll
                    for (int i = 0; i < 4; i++) {
                        float v = (rok && (k+i) < K) ? __bfloat162float(Ar[k+i]) : 0.f;
                        dp[i] = __float_as_uint(v) & 0xFFFFE000u;
                    }
                }
            } else {
                const float* Ar = (const float*)Araw
                                + (size_t)(rok ? (m0 + row) : 0) * K;
                float4 v = make_float4(0.f, 0.f, 0.f, 0.f);
                if (rok && (k + 3) < K) v = *(const float4*)(Ar + k);
                else {
                    float tt[4];
                    #pragma unroll
                    for (int i = 0; i < 4; i++) tt[i] = (rok && (k+i) < K) ? Ar[k+i] : 0.f;
                    v = make_float4(tt[0],tt[1],tt[2],tt[3]);
                }
                dp[0] = totf32(v.x); dp[1] = totf32(v.y);
                dp[2] = totf32(v.z); dp[3] = totf32(v.w);
            }
        }
        #pragma unroll
        for (int s = 0; s < 10; s++) {
            int idx = s * 256 + tid;
            if (idx < 304 * 8) {
                int row = idx >> 3, f4 = idx & 7;
                int k = kb + f4 * 4;
                float4 v = make_float4(0.f, 0.f, 0.f, 0.f);
                if (row < 300 && (k + 3) < K)
                    v = *(const float4*)(W + (size_t)row * K + k);
                uint32_t* dp = &sB[row * 36 + f4 * 4];
                dp[0] = totf32(v.x); dp[1] = totf32(v.y);
                dp[2] = totf32(v.z); dp[3] = totf32(v.w);
            }
        }
        __syncthreads();
        #pragma unroll
        for (int ks = 0; ks < 4; ks++) {
            int k0 = ks * 8;
            uint32_t a[2][4];
            #pragma unroll
            for (int i = 0; i < 2; i++) {
                int r = mrow + i * 16 + g;
                a[i][0] = sA[r * 36 + k0 + t];
                a[i][1] = sA[(r + 8) * 36 + k0 + t];
                a[i][2] = sA[r * 36 + k0 + t + 4];
                a[i][3] = sA[(r + 8) * 36 + k0 + t + 4];
            }
            #pragma unroll
            for (int nt = 0; nt < 19; nt++) {
                int n = (nbase + nt * 8 + g) * 36 + k0;
                uint32_t b0 = sB[n + t];
                uint32_t b1 = sB[n + t + 4];
                mma_tf32(d[0][nt], a[0], b0, b1);
                mma_tf32(d[1][nt], a[1], b0, b1);
            }
        }
        __syncthreads();
    }
    #pragma unroll
    for (int i = 0; i < 2; i++) {
        int r1 = m0 + mrow + i * 16 + g;
        int r2 = r1 + 8;
        #pragma unroll
        for (int nt = 0; nt < 19; nt++) {
            int col = nbase + nt * 8 + 2 * t;
            if (col >= 300) continue;
            float b0 = bias[col], b1 = bias[col + 1];
            if (r1 < M) {
                __nv_bfloat162 v;
                v.x = __float2bfloat16_rn(d[i][nt][0] + b0);
                v.y = __float2bfloat16_rn(d[i][nt][1] + b1);
                *(__nv_bfloat162*)(C + (size_t)r1 * 300 + col) = v;
            }
            if (r2 < M) {
                __nv_bfloat162 v;
                v.x = __float2bfloat16_rn(d[i][nt][2] + b0);
                v.y = __float2bfloat16_rn(d[i][nt][3] + b1);
                *(__nv_bfloat162*)(C + (size_t)r2 * 300 + col) = v;
            }
        }
    }
}

// ---------------- SGEMM v4 (SIMT, small GEMMs) --------------------------------
template<int BT, int QN>
__global__ __launch_bounds__(256) void sgemm4(
    const float* __restrict__ A, const float* __restrict__ B,
    const float* __restrict__ bias, float* __restrict__ C,
    int M, int N, int K, int act, int n0base)
{
    __shared__ __align__(16) float As[16][132];
    __shared__ __align__(16) float Bs[16][212];
    int tid = threadIdx.x;
    int m0 = blockIdx.y * 128;
    int n0 = blockIdx.x * (QN * 16) + n0base;

    int ra = tid >> 1, ka = (tid & 1) * 8;
    int gmA = m0 + ra;
    bool rokA = gmA < M;
    const float* Arow = A + (size_t)(rokA ? gmA : 0) * K;
    bool kal = ((K & 3) == 0);

    int rb, kb;
    const float* Brow = nullptr;
    bool rokB = true;
    if (BT) {
        rb = tid >> 1; kb = (tid & 1) * 8;
        rokB = (rb < QN * 16) && (n0 + rb) < N;
        Brow = B + (size_t)(rokB ? (n0 + rb) : 0) * K;
    } else {
        rb = tid >> 4; kb = (tid & 15) * 16;
    }

    float4 rA0, rA1;
    float rBv[16];

    auto fetch = [&](int k0) {
        rA0 = make_float4(0.f,0.f,0.f,0.f); rA1 = rA0;
        if (rokA) {
            int k = k0 + ka;
            if (kal && (k + 7) < K) {
                rA0 = *(const float4*)(Arow + k);
                rA1 = *(const float4*)(Arow + k + 4);
            } else {
                float t[8];
                #pragma unroll
                for (int i = 0; i < 8; i++) t[i] = ((k+i) < K) ? Arow[k+i] : 0.f;
                rA0 = make_float4(t[0],t[1],t[2],t[3]);
                rA1 = make_float4(t[4],t[5],t[6],t[7]);
            }
        }
        if (BT) {
            if (rokB) {
                int k = k0 + kb;
                #pragma unroll
                for (int i = 0; i < 8; i++)
                    rBv[i] = ((k+i) < K) ? Brow[k+i] : 0.f;
            } else {
                #pragma unroll
                for (int i = 0; i < 8; i++) rBv[i] = 0.f;
            }
        } else {
            int kk = k0 + rb;
            #pragma unroll
            for (int i = 0; i < 16; i++) {
                int col = n0 + kb + i;
                rBv[i] = (kk < K && kb + i < QN*16 && col < N)
                         ? B[(size_t)kk * N + col] : 0.f;
            }
        }
    };
    auto stage = [&]() {
        As[ka+0][ra]=rA0.x; As[ka+1][ra]=rA0.y; As[ka+2][ra]=rA0.z; As[ka+3][ra]=rA0.w;
        As[ka+4][ra]=rA1.x; As[ka+5][ra]=rA1.y; As[ka+6][ra]=rA1.z; As[ka+7][ra]=rA1.w;
        if (BT) {
            if (rb < QN*16) {
                #pragma unroll
                for (int i = 0; i < 8; i++) Bs[kb+i][rb] = rBv[i];
            }
        } else {
            #pragma unroll
            for (int i = 0; i < 16; i++)
                if (kb + i < QN*16) Bs[rb][kb+i] = rBv[i];
        }
    };

    u64 acc[4][QN];
    #pragma unroll
    for (int p = 0; p < 4; p++)
        #pragma unroll
        for (int q = 0; q < QN; q++) acc[p][q] = 0ull;

    int ty = tid >> 4, tx = tid & 15;
    int i0 = ty * 8;
    int T = (K + 15) / 16;
    fetch(0);
    for (int t = 0; t < T; t++) {
        stage();
        __syncthreads();
        if (t + 1 < T) fetch((t + 1) * 16);
        #pragma unroll
        for (int k = 0; k < 16; k++) {
            u64 a2[4];
            #pragma unroll
            for (int p = 0; p < 4; p++)
                a2[p] = *(const u64*)&As[k][i0 + 2*p];
            #pragma unroll
            for (int q = 0; q < QN; q++) {
                u64 bb = bc2(Bs[k][q*16 + tx]);
                #pragma unroll
                for (int p = 0; p < 4; p++) fma2(acc[p][q], a2[p], bb);
            }
        }
        __syncthreads();
    }

    #pragma unroll
    for (int p = 0; p < 4; p++) {
        int m1 = m0 + i0 + 2*p, m2 = m1 + 1;
        #pragma unroll
        for (int q = 0; q < QN; q++) {
            int n = n0 + q*16 + tx;
            if (n >= N) continue;
            float lo, hi; up2(acc[p][q], lo, hi);
            if (m1 < M) {
                float v = lo; if (bias) v += bias[n];
                if (act == 1) v = fmaxf(v, 0.f);
                C[(size_t)m1*N+n] = v;
            }
            if (m2 < M) {
                float v = hi; if (bias) v += bias[n];
                if (act == 1) v = fmaxf(v, 0.f);
                C[(size_t)m2*N+n] = v;
            }
        }
    }
}

// ---------------- persistent GRU layer (tensor GEMM + balanced gates) --------
#define GRU_SMEM (53384*4)

template<int LAYER>
__global__ __launch_bounds__(256) void gru_persist(
    const __nv_bfloat16* __restrict__ GIsrc,
    const int*   __restrict__ gnf,
    const float* __restrict__ whh, const float* __restrict__ bhh,
    const float* __restrict__ h0,
    __nv_bfloat16* __restrict__ Yb, float* __restrict__ Yf)
{
    extern __shared__ float sm[];
    uint32_t* sWt  = (uint32_t*)sm;            // [320][108]
    uint32_t* sHta = (uint32_t*)(sm + 34560);  // [32][108]
    float* sG  = sm + 38016;                   // [32][332]
    float* sHT = sm + 48640;                   // [100][34]
    float* sB  = sm + 52040;                   // [320]
    int*  sTok = (int*)(sm + 52360);           // [1024]
    int tid = threadIdx.x;
    int w = tid >> 5, lane = tid & 31;
    int g = lane >> 2, t = lane & 3;
    int w5 = w * 5;
    int rowbase = blockIdx.x * 32;

    for (int idx = tid; idx < 320 * 108; idx += 256) {
        int col = idx / 108, k = idx - col * 108;
        float v = (col < 300 && k < 100) ? whh[col * 100 + k] : 0.f;
        sWt[idx] = totf32(v);
    }
    for (int idx = tid; idx < 32 * 108; idx += 256) {
        int r = idx / 108, k = idx - r * 108;
        float v = (k < 100) ? h0[(size_t)(rowbase + r) * 100 + k] : 0.f;
        sHta[idx] = totf32(v);
    }
    for (int idx = tid; idx < 3200; idx += 256) {
        int r = idx / 100, c = idx - r * 100;
        sHT[c*34 + r] = h0[(size_t)(rowbase + r)*100 + c];
    }
    for (int idx = tid; idx < 320; idx += 256) sB[idx] = (idx < 300) ? bhh[idx] : 0.f;
    if (LAYER == 0) {
        for (int idx = tid; idx < 1024; idx += 256)
            sTok[idx] = gnf[rowbase * SEQL + idx];
    }
    __syncthreads();

    int pr[13], pc[13];
    #pragma unroll
    for (int q = 0; q < 13; q++) {
        int cell = tid + q * 256;
        pr[q] = cell / 100;
        pc[q] = cell - pr[q] * 100;
    }

    for (int s = 0; s < SEQL; s++) {
        float pg[13][3];
        #pragma unroll
        for (int q = 0; q < 13; q++) {
            int cell = tid + q * 256;
            if (cell < 3200) {
                int r = pr[q], c = pc[q];
                const __nv_bfloat16* gi;
                if (LAYER == 0) {
                    int tok = sTok[r * SEQL + s];
                    gi = GIsrc + (size_t)tok * 300;
                } else {
                    gi = GIsrc + ((size_t)s * NTW + (rowbase + r)) * 300;
                }
                pg[q][0] = __bfloat162float(gi[c]);
                pg[q][1] = __bfloat162float(gi[c + 100]);
                pg[q][2] = __bfloat162float(gi[c + 200]);
            }
        }

        float dfr[2][5][4];
        #pragma unroll
        for (int i = 0; i < 2; i++)
            #pragma unroll
            for (int j = 0; j < 5; j++)
                #pragma unroll
                for (int q = 0; q < 4; q++) dfr[i][j][q] = 0.f;

        #pragma unroll
        for (int ks = 0; ks < 13; ks++) {
            int k0 = ks * 8;
            uint32_t a[2][4];
            #pragma unroll
            for (int i = 0; i < 2; i++) {
                int r = i * 16 + g;
                a[i][0] = sHta[r * 108 + k0 + t];
                a[i][1] = sHta[(r + 8) * 108 + k0 + t];
                a[i][2] = sHta[r * 108 + k0 + t + 4];
                a[i][3] = sHta[(r + 8) * 108 + k0 + t + 4];
            }
            #pragma unroll
            for (int j = 0; j < 5; j++) {
                int cb = (w5 + j) * 8 + g;
                uint32_t b0 = sWt[cb * 108 + k0 + t];
                uint32_t b1 = sWt[cb * 108 + k0 + t + 4];
                mma_tf32(dfr[0][j], a[0], b0, b1);
                mma_tf32(dfr[1][j], a[1], b0, b1);
            }
        }
        #pragma unroll
        for (int i = 0; i < 2; i++) {
            int r1 = i * 16 + g, r2 = r1 + 8;
            #pragma unroll
            for (int j = 0; j < 5; j++) {
                int col = (w5 + j) * 8 + 2 * t;
                sG[r1 * 332 + col]     = dfr[i][j][0];
                sG[r1 * 332 + col + 1] = dfr[i][j][1];
                sG[r2 * 332 + col]     = dfr[i][j][2];
                sG[r2 * 332 + col + 1] = dfr[i][j][3];
            }
        }
        __syncthreads();

        #pragma unroll
        for (int q = 0; q < 13; q++) {
            int cell = tid + q * 256;
            if (cell < 3200) {
                int r = pr[q], c = pc[q];
                float hr  = sG[r*332 + c]       + sB[c];
                float hz  = sG[r*332 + c + 100] + sB[c+100];
                float hnn = sG[r*332 + c + 200] + sB[c+200];
                float h   = sHT[c*34 + r];
                float rg = sigmoid_ffma(pg[q][0] + hr);
                float zg = __fdividef(1.f, 1.f + __expf(-(pg[q][1] + hz)));
                float x  = pg[q][2] + rg * hnn;
                float tt = __expf(-2.f * fabsf(x));
                float ng = copysignf(__fdividef(1.f - tt, 1.f + tt), x);
                float hn = (1.f - zg) * ng + zg * h;
                sHT[c*34 + r] = hn;
                sHta[r*108 + c] = totf32(hn);
                if (LAYER == 0)
                    Yb[((size_t)s * NTW + (rowbase + r)) * 100 + c] =
                        __float2bfloat16_rn(hn);
            }
        }
        __syncthreads();
    }
    if (LAYER == 1) {
        for (int ii = tid; ii < 3200; ii += 256) {
            int r = ii / 100, c = ii - r * 100;
            int grow = rowbase + r;
            int orow = (grow < BSZ) ? grow : grow + NUSR;
            Yf[(size_t)orow * 100 + c] = sHT[c*34 + r];
        }
    }
}

// ---------------- graph structure kernels ------------------------------------
__global__ void k_zero3(double* accP, double* accW, double* accK) {
    int i = threadIdx.x;
    if (i < 96) { accP[i] = 0.0; accW[i] = 0.0; }
    if (i < 64) accK[i] = 0.0;
}
__global__ void k_cat(const float* __restrict__ cmw, const float* __restrict__ clw,
                      float* __restrict__ wcat) {
    int i = blockIdx.x * 256 + threadIdx.x;
    if (i >= 64 * 200) return;
    int k = i / 200, c = i - k * 200;
    wcat[i] = (c < 100) ? cmw[k * 100 + c] : clw[k * 100 + (c - 100)];
}
__global__ void k_scatter_cnt(const int* __restrict__ src, const int* __restrict__ dst,
                              unsigned* __restrict__ cnt, unsigned* __restrict__ cntT,
                              int* __restrict__ deg) {
    int e = blockIdx.x * 256 + threadIdx.x;
    if (e >= NEDGE) return;
    int s = src[e], d = dst[e];
    size_t idx  = (size_t)s * NN + d;
    size_t idxT = (size_t)d * NN + s;
    atomicAdd(&cnt [idx  >> 2], 1u << ((idx  & 3) * 8));
    atomicAdd(&cntT[idxT >> 2], 1u << ((idxT & 3) * 8));
    atomicAdd(&deg[d], 1);
}
__global__ __launch_bounds__(1024) void k_prefix(const int* __restrict__ cnt,
                                                 int* __restrict__ rowptr,
                                                 int* __restrict__ fill,
                                                 float* __restrict__ dis) {
    __shared__ int part[1024];
    int tid = threadIdx.x;
    int base = tid * 6;
    int loc[6], cv[6];
    int s = 0;
    #pragma unroll
    for (int i = 0; i < 6; i++) { cv[i] = cnt[base + i]; loc[i] = s; s += cv[i]; }
    part[tid] = s;
    __syncthreads();
    for (int o = 1; o < 1024; o <<= 1) {
        int t = (tid >= o) ? part[tid - o] : 0;
        __syncthreads();
        part[tid] += t;
        __syncthreads();
    }
    int excl = part[tid] - s;
    #pragma unroll
    for (int i = 0; i < 6; i++) {
        rowptr[base + i] = excl + loc[i];
        fill[base + i] = 0;
        dis[base + i] = rsqrtf((float)cv[i] + 1.f);
    }
    if (tid == 1023) rowptr[NN] = part[1023];
}
__global__ void k_fill(const int* __restrict__ src, const int* __restrict__ dst,
                       const int* __restrict__ rowptr, int* __restrict__ fill,
                       const float* __restrict__ dis,
                       int* __restrict__ esrc, float* __restrict__ ecoef) {
    int e = blockIdx.x * 256 + threadIdx.x;
    if (e >= NEDGE) return;
    int s = src[e], d = dst[e];
    int pos = rowptr[d] + atomicAdd(&fill[d], 1);
    esrc[pos] = s;
    ecoef[pos] = dis[s] * dis[d];
}

// ---------------- CSR aggregation kernels -------------------------------------
__global__ __launch_bounds__(256) void k_agg1(
    const float* __restrict__ xw, const float* __restrict__ b,
    const int* __restrict__ rowptr, const int* __restrict__ esrc,
    const float* __restrict__ ecoef, const float* __restrict__ dis,
    float* __restrict__ outv)
{
    int task = blockIdx.x * 8 + (threadIdx.x >> 5);
    int lane = threadIdx.x & 31;
    int n = task >> 1;
    int c = ((task & 1) << 5) + lane;
    if (n >= NN) return;
    float dn = dis[n];
    float v = xw[(size_t)n*64 + c] * dn * dn + b[c];
    int p1 = rowptr[n+1];
    for (int p = rowptr[n]; p < p1; p++) {
        int s = esrc[p];
        v = fmaf(xw[(size_t)s*64 + c], ecoef[p], v);
    }
    outv[(size_t)n*64 + c] = (v > 0.f) ? v : expm1f(v);
}
__global__ __launch_bounds__(256) void k_aggmulv(
    const float* __restrict__ xwc,
    const float* __restrict__ bm, const float* __restrict__ bl,
    const int* __restrict__ rowptr, const int* __restrict__ esrc,
    const float* __restrict__ ecoef, const float* __restrict__ dis,
    const float* __restrict__ eps, float* __restrict__ Z,
    float* __restrict__ out, double* __restrict__ accK)
{
    __shared__ float wred[8];
    int task = blockIdx.x * 8 + (threadIdx.x >> 5);
    int lane = threadIdx.x & 31;
    int n = task >> 2;
    int c = ((task & 3) << 5) + lane;
    float kl = 0.f;
    if (n < NN && c < 100) {
        float dn = dis[n];
        float d2 = dn * dn;
        float vm = fmaf(xwc[(size_t)n*200 + c],       d2, bm[c]);
        float vl = fmaf(xwc[(size_t)n*200 + 100 + c], d2, bl[c]);
        int p1 = rowptr[n+1];
        for (int p = rowptr[n]; p < p1; p++) {
            int s = esrc[p];
            float co = ecoef[p];
            vm = fmaf(xwc[(size_t)s*200 + c],       co, vm);
            vl = fmaf(xwc[(size_t)s*200 + 100 + c], co, vl);
        }
        float mu = fmaxf(vm, 0.f);
        float lv = fmaxf(vl, 0.f);
        float z = fmaf(expf(lv * 0.5f), eps[(size_t)n*100 + c], mu);
        Z[(size_t)n*100 + c] = z;
        if (n < BSZ) out[(size_t)n*100 + c] = z;
        kl = -0.5f * (1.f + lv - mu*mu - expf(lv));
    }
    #pragma unroll
    for (int o = 16; o > 0; o >>= 1)
        kl += __shfl_down_sync(0xFFFFFFFFu, kl, o);
    if (lane == 0) wred[threadIdx.x >> 5] = kl;
    __syncthreads();
    if (threadIdx.x == 0) {
        float t = 0.f;
        #pragma unroll
        for (int w = 0; w < 8; w++) t += wred[w];
        atomicAdd(&accK[blockIdx.x & 63], (double)t);
    }
}

// ---------------- Z@Z^T loss: tensor dot + reduced-MUFU epilogue --------------
#define ZZT_SMEM (2*64*108*4)
__global__ __launch_bounds__(256) void k_zzt7(const float* __restrict__ Z,
                                              const unsigned* __restrict__ cnt,
                                              const unsigned* __restrict__ cntT,
                                              double* __restrict__ accP,
                                              double* __restrict__ accW) {
    int q = blockIdx.x;
    int bjB = (int)((sqrt(8.0 * q + 1.0) - 1.0) * 0.5);
    while ((bjB + 1) * (bjB + 2) / 2 <= q) bjB++;
    while (bjB * (bjB + 1) / 2 > q) bjB--;
    int biB = q - bjB * (bjB + 1) / 2;

    extern __shared__ uint32_t zsm[];
    uint32_t* zA = zsm;
    uint32_t* zB = zsm + 64*108;
    int tid = threadIdx.x;
    int w = tid >> 5, lane = tid & 31;
    int g = lane >> 2, t = lane & 3;
    int bi = biB * 64, bj = bjB * 64;

    for (int f = tid; f < 64 * 104; f += 256) {
        int r = f / 104, k = f - r * 104;
        float va = (k < 100) ? Z[(size_t)(bi + r) * 100 + k] : 0.f;
        float vb = (k < 100) ? Z[(size_t)(bj + r) * 100 + k] : 0.f;
        zA[r * 108 + k] = totf32(va);
        zB[r * 108 + k] = totf32(vb);
    }
    __syncthreads();

    int mg = (w & 1) * 32;
    int ngrp = (w >> 1) * 16;

    float d[2][2][4];
    #pragma unroll
    for (int i = 0; i < 2; i++)
        #pragma unroll
        for (int j = 0; j < 2; j++)
            #pragma unroll
            for (int e = 0; e < 4; e++) d[i][j][e] = 0.f;

    #pragma unroll
    for (int ks = 0; ks < 13; ks++) {
        int k0 = ks * 8;
        uint32_t a[2][4];
        #pragma unroll
        for (int i = 0; i < 2; i++) {
            int r = mg + i * 16 + g;
            a[i][0] = zA[r * 108 + k0 + t];
            a[i][1] = zA[(r + 8) * 108 + k0 + t];
            a[i][2] = zA[r * 108 + k0 + t + 4];
            a[i][3] = zA[(r + 8) * 108 + k0 + t + 4];
        }
        #pragma unroll
        for (int j = 0; j < 2; j++) {
            int cb = ngrp + j * 8 + g;
            uint32_t b0 = zB[cb * 108 + k0 + t];
            uint32_t b1 = zB[cb * 108 + k0 + t + 4];
            mma_tf32(d[0][j], a[0], b0, b1);
            mma_tf32(d[1][j], a[1], b0, b1);
        }
    }

    bool diag = (biB == bjB);
    float sp = 0.f, sw = 0.f;
    #pragma unroll
    for (int i = 0; i < 2; i++) {
        #pragma unroll
        for (int half = 0; half < 2; half++) {
            int iloc = mg + i * 16 + g + half * 8;
            int ig = bi + iloc;
            #pragma unroll
            for (int j = 0; j < 2; j++) {
                int cloc = ngrp + j * 8 + 2 * t;
                int jg = bj + cloc;
                unsigned wrow  = cnt [(size_t)ig * (NN/4) + ((unsigned)jg >> 2)];
                unsigned wrowT = diag ? 0u
                               : cntT[(size_t)ig * (NN/4) + ((unsigned)jg >> 2)];
                #pragma unroll
                for (int e = 0; e < 2; e++) {
                    float zv = d[i][j][half * 2 + e];
                    int col = jg + e;
                    float u = __expf(-fabsf(zv));
                    float r = recip1p(u);
                    float s = (zv >= 0.f) ? r : u * r;
                    float lg = __logf(1.f + u);
                    float mlogp, mlog1mp;
                    if (zv > 15.942384f) {
                        mlogp = 1.1920929e-7f; mlog1mp = 15.9423847f;
                    } else if (zv < -16.118095f) {
                        mlogp = 16.118095f;    mlog1mp = 1.0000000e-7f;
                    } else {
                        mlogp = (zv >= 0.f) ? lg : (lg - zv);
                        mlog1mp = zv + mlogp;
                    }
                    float ag1 = (float)((wrow >> ((col & 3) * 8)) & 0xFFu)
                              + ((ig == col) ? 1.f : 0.f);
                    float wg1 = (ag1 == 1.f) ? PWc : 1.f;
                    sp += s;
                    sw += wg1 * (ag1 * mlogp + (1.f - ag1) * mlog1mp);
                    if (!diag) {
                        float ag2 = (float)((wrowT >> ((col & 3) * 8)) & 0xFFu);
                        float wg2 = (ag2 == 1.f) ? PWc : 1.f;
                        sp += s;
                        sw += wg2 * (ag2 * mlogp + (1.f - ag2) * mlog1mp);
                    }
                }
            }
        }
    }
    __syncthreads();
    double* red = (double*)zsm;
    red[tid] = (double)sp; __syncthreads();
    for (int o = 128; o > 0; o >>= 1) {
        if (tid < o) red[tid] += red[tid + o];
        __syncthreads();
    }
    if (tid == 0) atomicAdd(&accP[bjB], red[0]);
    __syncthreads();
    red[tid] = (double)sw; __syncthreads();
    for (int o = 128; o > 0; o >>= 1) {
        if (tid < o) red[tid] += red[tid + o];
        __syncthreads();
    }
    if (tid == 0) atomicAdd(&accW[bjB], red[0]);
}

__global__ void k_fin(const double* __restrict__ accP, const double* __restrict__ accW,
                      const double* __restrict__ accK, float* __restrict__ out) {
    double sp = 0.0, sw = 0.0, sk = 0.0;
    for (int i = 0; i < 96; i++) { sp += accP[i]; sw += accW[i]; }
    for (int i = 0; i < 64; i++) sk += accK[i];
    double norm = N2D / ((N2D - sp) * 2.0);
    out[BSZ * 100]     = (float)(sk / (double)NN);
    out[BSZ * 100 + 1] = (float)(norm * (sw / N2D));
}

// ---------------- host launch ------------------------------------------------
extern "C" void kernel_launch(void* const* d_in, const int* in_sizes, int n_in,
                              void* d_out, int out_size) {
    const float* user_feats = (const float*)d_in[0];
    const int*   gnf        = (const int*)  d_in[1];
    const int*   eidx       = (const int*)  d_in[2];
    const float* h0         = (const float*)d_in[4];
    const float* eps        = (const float*)d_in[5];
    const float* emb        = (const float*)d_in[6];
    const float* mw1 = (const float*)d_in[7],  *mb1 = (const float*)d_in[8];
    const float* mw2 = (const float*)d_in[9],  *mb2 = (const float*)d_in[10];
    const float* wih0 = (const float*)d_in[11], *whh0 = (const float*)d_in[12];
    const float* bih0 = (const float*)d_in[13], *bhh0 = (const float*)d_in[14];
    const float* wih1 = (const float*)d_in[15], *whh1 = (const float*)d_in[16];
    const float* bih1 = (const float*)d_in[17], *bhh1 = (const float*)d_in[18];
    const float* c1w = (const float*)d_in[19], *c1b = (const float*)d_in[20];
    const float* cmw = (const float*)d_in[21], *cmb = (const float*)d_in[22];
    const float* clw = (const float*)d_in[23], *clb = (const float*)d_in[24];
    float* out = (float*)d_out;
    const int* srcp = eidx;
    const int* dstp = eidx + NEDGE;

    void* p;
    cudaGetSymbolAddress(&p, g_Gi);  __nv_bfloat16* GiB = (__nv_bfloat16*)p;
    cudaGetSymbolAddress(&p, g_Y0);  __nv_bfloat16* Y0B = (__nv_bfloat16*)p;
    cudaGetSymbolAddress(&p, g_T1);  float* T1  = (float*)p;
    cudaGetSymbolAddress(&p, g_Xin); float* Xin = (float*)p;
    cudaGetSymbolAddress(&p, g_XW);  float* XW1 = (float*)p;
    cudaGetSymbolAddress(&p, g_XWc); float* XWc = (float*)p;
    cudaGetSymbolAddress(&p, g_Wcat); float* Wcat = (float*)p;
    cudaGetSymbolAddress(&p, g_Hc);  float* Hc  = (float*)p;
    cudaGetSymbolAddress(&p, g_Z);   float* Z   = (float*)p;
    cudaGetSymbolAddress(&p, g_dis); float* dis = (float*)p;
    cudaGetSymbolAddress(&p, g_cnt);    int* cntI = (int*)p;
    cudaGetSymbolAddress(&p, g_rowptr); int* rowptr = (int*)p;
    cudaGetSymbolAddress(&p, g_fill);   int* fill = (int*)p;
    cudaGetSymbolAddress(&p, g_esrc);   int* esrc = (int*)p;
    cudaGetSymbolAddress(&p, g_ecoef);  float* ecoef = (float*)p;
    cudaGetSymbolAddress(&p, g_Acnt);   unsigned* Acnt = (unsigned*)p;
    cudaGetSymbolAddress(&p, g_AcntT);  unsigned* AcntT = (unsigned*)p;
    cudaGetSymbolAddress(&p, g_accP);   double* accP = (double*)p;
    cudaGetSymbolAddress(&p, g_accW);   double* accW = (double*)p;
    cudaGetSymbolAddress(&p, g_accK);   double* accK = (double*)p;

    static bool inited = false;
    static cudaStream_t s2;
    static cudaEvent_t evRoot, evSetup;
    if (!inited) {
        cudaStreamCreateWithFlags(&s2, cudaStreamNonBlocking);
        cudaEventCreateWithFlags(&evRoot,  cudaEventDisableTiming);
        cudaEventCreateWithFlags(&evSetup, cudaEventDisableTiming);
        cudaFuncSetAttribute(gru_persist<0>, cudaFuncAttributeMaxDynamicSharedMemorySize, GRU_SMEM);
        cudaFuncSetAttribute(gru_persist<1>, cudaFuncAttributeMaxDynamicSharedMemorySize, GRU_SMEM);
        cudaFuncSetAttribute(k_zzt7, cudaFuncAttributeMaxDynamicSharedMemorySize, ZZT_SMEM);
        cudaFuncSetAttribute(wgemm_tf32<0>, cudaFuncAttributeMaxDynamicSharedMemorySize, WG_SMEM);
        cudaFuncSetAttribute(wgemm_tf32<1>, cudaFuncAttributeMaxDynamicSharedMemorySize, WG_SMEM);
        inited = true;
    }

    cudaEventRecord(evRoot, 0);

    // ---- side stream s2: graph setup + user MLP + weight concat ----
    cudaStreamWaitEvent(s2, evRoot, 0);
    cudaMemsetAsync(Acnt,  0, (size_t)NN * (NN/4) * sizeof(unsigned), s2);
    cudaMemsetAsync(AcntT, 0, (size_t)NN * (NN/4) * sizeof(unsigned), s2);
    cudaMemsetAsync(cntI, 0, NN * sizeof(int), s2);
    k_zero3<<<1, 128, 0, s2>>>(accP, accW, accK);
    k_cat<<<50, 256, 0, s2>>>(cmw, clw, Wcat);
    k_scatter_cnt<<<(NEDGE + 255)/256, 256, 0, s2>>>(srcp, dstp, Acnt, AcntT, cntI);
    k_prefix<<<1, 1024, 0, s2>>>(cntI, rowptr, fill, dis);
    k_fill<<<(NEDGE + 255)/256, 256, 0, s2>>>(srcp, dstp, rowptr, fill, dis, esrc, ecoef);
    sgemm4<0,7><<<dim3(1, 16), 256, 0, s2>>>(user_feats, mw1, mb1, T1, NUSR, 100, 9, 1, 0);
    sgemm4<0,7><<<dim3(1, 16), 256, 0, s2>>>(T1, mw2, mb2, Xin + (size_t)BSZ*100, NUSR, 100, 100, 0, 0);
    cudaEventRecord(evSetup, s2);

    // ---- main: E2G (warp-MMA tf32 -> bf16) ----
    wgemm_tf32<0><<<(VOCAB + 127)/128, 256, WG_SMEM>>>(emb, wih0, bih0, GiB, VOCAB, 300, 10);

    gru_persist<0><<<128, 256, GRU_SMEM>>>(GiB, gnf, whh0, bhh0, h0, Y0B, nullptr);

    // ---- Gi1 (warp-MMA tf32, bf16 A -> bf16 out) ----
    wgemm_tf32<1><<<RALL/128, 256, WG_SMEM>>>(Y0B, wih1, bih1, GiB, RALL, 100, 4);

    gru_persist<1><<<128, 256, GRU_SMEM>>>(GiB, nullptr, whh1, bhh1,
                                           h0 + (size_t)NTW*HID, nullptr, Xin);

    // join setup (CSR + UE rows of Xin + Wcat) before convs
    cudaStreamWaitEvent(0, evSetup, 0);

    // conv1 -> elu
    sgemm4<0,4><<<dim3(1, 48), 256>>>(Xin, c1w, nullptr, XW1, NN, 64, 100, 0, 0);
    k_agg1<<<NN*2/8, 256>>>(XW1, c1b, rowptr, esrc, ecoef, dis, Hc);

    // convmu + convlv in one GEMM (N=200 concat)
    sgemm4<0,13><<<dim3(1, 48), 256>>>(Hc, Wcat, nullptr, XWc, NN, 200, 64, 0, 0);

    k_aggmulv<<<NN*4/8, 256>>>(XWc, cmb, clb, rowptr, esrc, ecoef, dis,
                               eps, Z, out, accK);

    k_zzt7<<<96*97/2, 256, ZZT_SMEM>>>(Z, Acnt, AcntT, accP, accW);
    k_fin<<<1, 1>>>(accP, accW, accK, out);
}

// round 17
// speedup vs baseline: 1.0886x; 1.0145x over previous
#include <cuda_runtime.h>
#include <cuda_bf16.h>
#include <math.h>
#include <stdint.h>

typedef unsigned long long u64;

#define NTW   4096
#define NUSR  2048
#define NN    6144
#define NEDGE 98304
#define SEQL  32
#define EMB   300
#define HID   100
#define BSZ   2048
#define VOCAB 50000
#define RALL  (NTW*SEQL)          /* 131072 */
#define N2D   37748736.0          /* NN*NN */
#define PWc   ((float)((37748736.0-104448.0)/104448.0))

// ---------------- f32x2 helpers ---------------------------------------------
__device__ __forceinline__ u64 bc2(float x) {
    u64 r; asm("mov.b64 %0, {%1, %1};" : "=l"(r) : "f"(x)); return r;
}
__device__ __forceinline__ void up2(u64 v, float& lo, float& hi) {
    asm("mov.b64 {%0, %1}, %2;" : "=f"(lo), "=f"(hi) : "l"(v));
}
__device__ __forceinline__ void fma2(u64& d, u64 a, u64 b) {
    asm("fma.rn.f32x2 %0, %1, %2, %0;" : "+l"(d) : "l"(a), "l"(b));
}

// ---------------- warp MMA tf32 helpers ---------------------------------------
__device__ __forceinline__ uint32_t totf32(float x) {
    uint32_t r; asm("cvt.rna.tf32.f32 %0, %1;" : "=r"(r) : "f"(x)); return r;
}
__device__ __forceinline__ void mma_tf32(float* d, const uint32_t* a,
                                         uint32_t b0, uint32_t b1) {
    asm volatile(
        "mma.sync.aligned.m16n8k8.row.col.f32.tf32.tf32.f32 "
        "{%0,%1,%2,%3}, {%4,%5,%6,%7}, {%8,%9}, {%0,%1,%2,%3};"
        : "+f"(d[0]), "+f"(d[1]), "+f"(d[2]), "+f"(d[3])
        : "r"(a[0]), "r"(a[1]), "r"(a[2]), "r"(a[3]), "r"(b0), "r"(b1));
}

// ---------------- FFMA-only special functions ---------------------------------
__device__ __forceinline__ float exp_neg(float a) {
    a = fminf(a, 80.f);
    float t = a * -1.4426950408889634f;
    float nf = floorf(t);
    float f = t - nf;
    float p = 1.3215486790144307e-06f;
    p = fmaf(p, f, 1.5252733804059841e-05f);
    p = fmaf(p, f, 1.5403530393381606e-04f);
    p = fmaf(p, f, 1.3333558146428443e-03f);
    p = fmaf(p, f, 9.6181291076284772e-03f);
    p = fmaf(p, f, 5.5504108664821580e-02f);
    p = fmaf(p, f, 2.4022650695910072e-01f);
    p = fmaf(p, f, 6.9314718055994531e-01f);
    p = fmaf(p, f, 1.0f);
    return p * __int_as_float(((int)nf + 127) << 23);
}
__device__ __forceinline__ float recip1p(float u) {
    float D = fmaf(0.5f, u, 0.5f);
    float x = fmaf(-1.88235294f, D, 2.82352941f);
    x = fmaf(x, fmaf(-D, x, 1.f), x);
    x = fmaf(x, fmaf(-D, x, 1.f), x);
    x = fmaf(x, fmaf(-D, x, 1.f), x);
    return 0.5f * x;
}
__device__ __forceinline__ float sigmoid_ffma(float x) {
    float u = exp_neg(fabsf(x));
    float r = recip1p(u);
    return (x >= 0.f) ? r : u * r;
}

// ---------------- scratch ---------------------------------------------------
__device__ __nv_bfloat16 g_Gi [(size_t)RALL*300];
__device__ __nv_bfloat16 g_Y0 [(size_t)RALL*HID];
__device__ float    g_T1 [NUSR*100];
__device__ float    g_Xin[NN*100];
__device__ float    g_XW [NN*100];
__device__ float    g_XWc[NN*200];
__device__ float    g_Wcat[64*200];
__device__ float    g_Hc [NN*64];
__device__ float    g_Z  [NN*100];
__device__ float    g_dis[NN];
__device__ int      g_cnt[NN];
__device__ int      g_rowptr[NN+1];
__device__ int      g_fill[NN];
__device__ int      g_esrc[NEDGE];
__device__ float    g_ecoef[NEDGE];
__device__ unsigned g_Acnt [(size_t)NN*(NN/4)];
__device__ unsigned g_AcntT[(size_t)NN*(NN/4)];
__device__ double   g_accP[96];
__device__ double   g_accW[96];
__device__ double   g_accK[64];

// ---------------- warp-MMA tf32 GEMM -> bf16 out ------------------------------
#define WG_SMEM ((128*36 + 304*36) * 4)

template<int ABF>
__global__ __launch_bounds__(256) void wgemm_tf32(
    const void* __restrict__ Araw, const float* __restrict__ W,
    const float* __restrict__ bias, __nv_bfloat16* __restrict__ C,
    int M, int K, int nchunk)
{
    extern __shared__ uint32_t wsm[];
    uint32_t* sA = wsm;             // [128][36]
    uint32_t* sB = wsm + 128*36;    // [304][36]
    int tid = threadIdx.x;
    int w = tid >> 5, lane = tid & 31;
    int g = lane >> 2, t = lane & 3;
    int m0 = blockIdx.x * 128;
    int mrow = (w & 3) * 32;
    int nbase = (w >> 2) * 152;

    float d[2][19][4];
    #pragma unroll
    for (int i = 0; i < 2; i++)
        #pragma unroll
        for (int nt = 0; nt < 19; nt++)
            #pragma unroll
            for (int q = 0; q < 4; q++) d[i][nt][q] = 0.f;

    for (int c = 0; c < nchunk; c++) {
        int kb = c * 32;
        #pragma unroll
        for (int s = 0; s < 4; s++) {
            int idx = s * 256 + tid;
            int row = idx >> 3, f4 = idx & 7;
            int k = kb + f4 * 4;
            uint32_t* dp = &sA[row * 36 + f4 * 4];
            bool rok = (m0 + row) < M;
            if (ABF) {
                const __nv_bfloat16* Ar = (const __nv_bfloat16*)Araw
                                        + (size_t)(rok ? (m0 + row) : 0) * K;
                if (rok && (k + 3) < K) {
                    uint2 u = *(const uint2*)(Ar + k);
                    dp[0] = (u.x & 0xFFFFu) << 16; dp[1] = u.x & 0xFFFF0000u;
                    dp[2] = (u.y & 0xFFFFu) << 16; dp[3] = u.y & 0xFFFF0000u;
                } else {
                    #pragma unroll
                    for (int i = 0; i < 4; i++) {
                        float v = (rok && (k+i) < K) ? __bfloat162float(Ar[k+i]) : 0.f;
                        dp[i] = __float_as_uint(v) & 0xFFFFE000u;
                    }
                }
            } else {
                const float* Ar = (const float*)Araw
                                + (size_t)(rok ? (m0 + row) : 0) * K;
                float4 v = make_float4(0.f, 0.f, 0.f, 0.f);
                if (rok && (k + 3) < K) v = *(const float4*)(Ar + k);
                else {
                    float tt[4];
                    #pragma unroll
                    for (int i = 0; i < 4; i++) tt[i] = (rok && (k+i) < K) ? Ar[k+i] : 0.f;
                    v = make_float4(tt[0],tt[1],tt[2],tt[3]);
                }
                dp[0] = totf32(v.x); dp[1] = totf32(v.y);
                dp[2] = totf32(v.z); dp[3] = totf32(v.w);
            }
        }
        #pragma unroll
        for (int s = 0; s < 10; s++) {
            int idx = s * 256 + tid;
            if (idx < 304 * 8) {
                int row = idx >> 3, f4 = idx & 7;
                int k = kb + f4 * 4;
                float4 v = make_float4(0.f, 0.f, 0.f, 0.f);
                if (row < 300 && (k + 3) < K)
                    v = *(const float4*)(W + (size_t)row * K + k);
                uint32_t* dp = &sB[row * 36 + f4 * 4];
                dp[0] = totf32(v.x); dp[1] = totf32(v.y);
                dp[2] = totf32(v.z); dp[3] = totf32(v.w);
            }
        }
        __syncthreads();
        #pragma unroll
        for (int ks = 0; ks < 4; ks++) {
            int k0 = ks * 8;
            uint32_t a[2][4];
            #pragma unroll
            for (int i = 0; i < 2; i++) {
                int r = mrow + i * 16 + g;
                a[i][0] = sA[r * 36 + k0 + t];
                a[i][1] = sA[(r + 8) * 36 + k0 + t];
                a[i][2] = sA[r * 36 + k0 + t + 4];
                a[i][3] = sA[(r + 8) * 36 + k0 + t + 4];
            }
            #pragma unroll
            for (int nt = 0; nt < 19; nt++) {
                int n = (nbase + nt * 8 + g) * 36 + k0;
                uint32_t b0 = sB[n + t];
                uint32_t b1 = sB[n + t + 4];
                mma_tf32(d[0][nt], a[0], b0, b1);
                mma_tf32(d[1][nt], a[1], b0, b1);
            }
        }
        __syncthreads();
    }
    #pragma unroll
    for (int i = 0; i < 2; i++) {
        int r1 = m0 + mrow + i * 16 + g;
        int r2 = r1 + 8;
        #pragma unroll
        for (int nt = 0; nt < 19; nt++) {
            int col = nbase + nt * 8 + 2 * t;
            if (col >= 300) continue;
            float b0 = bias[col], b1 = bias[col + 1];
            if (r1 < M) {
                __nv_bfloat162 v;
                v.x = __float2bfloat16_rn(d[i][nt][0] + b0);
                v.y = __float2bfloat16_rn(d[i][nt][1] + b1);
                *(__nv_bfloat162*)(C + (size_t)r1 * 300 + col) = v;
            }
            if (r2 < M) {
                __nv_bfloat162 v;
                v.x = __float2bfloat16_rn(d[i][nt][2] + b0);
                v.y = __float2bfloat16_rn(d[i][nt][3] + b1);
                *(__nv_bfloat162*)(C + (size_t)r2 * 300 + col) = v;
            }
        }
    }
}

// ---------------- SGEMM v4 (SIMT, small GEMMs) --------------------------------
template<int BT, int QN>
__global__ __launch_bounds__(256) void sgemm4(
    const float* __restrict__ A, const float* __restrict__ B,
    const float* __restrict__ bias, float* __restrict__ C,
    int M, int N, int K, int act, int n0base)
{
    __shared__ __align__(16) float As[16][132];
    __shared__ __align__(16) float Bs[16][212];
    int tid = threadIdx.x;
    int m0 = blockIdx.y * 128;
    int n0 = blockIdx.x * (QN * 16) + n0base;

    int ra = tid >> 1, ka = (tid & 1) * 8;
    int gmA = m0 + ra;
    bool rokA = gmA < M;
    const float* Arow = A + (size_t)(rokA ? gmA : 0) * K;
    bool kal = ((K & 3) == 0);

    int rb, kb;
    const float* Brow = nullptr;
    bool rokB = true;
    if (BT) {
        rb = tid >> 1; kb = (tid & 1) * 8;
        rokB = (rb < QN * 16) && (n0 + rb) < N;
        Brow = B + (size_t)(rokB ? (n0 + rb) : 0) * K;
    } else {
        rb = tid >> 4; kb = (tid & 15) * 16;
    }

    float4 rA0, rA1;
    float rBv[16];

    auto fetch = [&](int k0) {
        rA0 = make_float4(0.f,0.f,0.f,0.f); rA1 = rA0;
        if (rokA) {
            int k = k0 + ka;
            if (kal && (k + 7) < K) {
                rA0 = *(const float4*)(Arow + k);
                rA1 = *(const float4*)(Arow + k + 4);
            } else {
                float t[8];
                #pragma unroll
                for (int i = 0; i < 8; i++) t[i] = ((k+i) < K) ? Arow[k+i] : 0.f;
                rA0 = make_float4(t[0],t[1],t[2],t[3]);
                rA1 = make_float4(t[4],t[5],t[6],t[7]);
            }
        }
        if (BT) {
            if (rokB) {
                int k = k0 + kb;
                #pragma unroll
                for (int i = 0; i < 8; i++)
                    rBv[i] = ((k+i) < K) ? Brow[k+i] : 0.f;
            } else {
                #pragma unroll
                for (int i = 0; i < 8; i++) rBv[i] = 0.f;
            }
        } else {
            int kk = k0 + rb;
            #pragma unroll
            for (int i = 0; i < 16; i++) {
                int col = n0 + kb + i;
                rBv[i] = (kk < K && kb + i < QN*16 && col < N)
                         ? B[(size_t)kk * N + col] : 0.f;
            }
        }
    };
    auto stage = [&]() {
        As[ka+0][ra]=rA0.x; As[ka+1][ra]=rA0.y; As[ka+2][ra]=rA0.z; As[ka+3][ra]=rA0.w;
        As[ka+4][ra]=rA1.x; As[ka+5][ra]=rA1.y; As[ka+6][ra]=rA1.z; As[ka+7][ra]=rA1.w;
        if (BT) {
            if (rb < QN*16) {
                #pragma unroll
                for (int i = 0; i < 8; i++) Bs[kb+i][rb] = rBv[i];
            }
        } else {
            #pragma unroll
            for (int i = 0; i < 16; i++)
                if (kb + i < QN*16) Bs[rb][kb+i] = rBv[i];
        }
    };

    u64 acc[4][QN];
    #pragma unroll
    for (int p = 0; p < 4; p++)
        #pragma unroll
        for (int q = 0; q < QN; q++) acc[p][q] = 0ull;

    int ty = tid >> 4, tx = tid & 15;
    int i0 = ty * 8;
    int T = (K + 15) / 16;
    fetch(0);
    for (int t = 0; t < T; t++) {
        stage();
        __syncthreads();
        if (t + 1 < T) fetch((t + 1) * 16);
        #pragma unroll
        for (int k = 0; k < 16; k++) {
            u64 a2[4];
            #pragma unroll
            for (int p = 0; p < 4; p++)
                a2[p] = *(const u64*)&As[k][i0 + 2*p];
            #pragma unroll
            for (int q = 0; q < QN; q++) {
                u64 bb = bc2(Bs[k][q*16 + tx]);
                #pragma unroll
                for (int p = 0; p < 4; p++) fma2(acc[p][q], a2[p], bb);
            }
        }
        __syncthreads();
    }

    #pragma unroll
    for (int p = 0; p < 4; p++) {
        int m1 = m0 + i0 + 2*p, m2 = m1 + 1;
        #pragma unroll
        for (int q = 0; q < QN; q++) {
            int n = n0 + q*16 + tx;
            if (n >= N) continue;
            float lo, hi; up2(acc[p][q], lo, hi);
            if (m1 < M) {
                float v = lo; if (bias) v += bias[n];
                if (act == 1) v = fmaxf(v, 0.f);
                C[(size_t)m1*N+n] = v;
            }
            if (m2 < M) {
                float v = hi; if (bias) v += bias[n];
                if (act == 1) v = fmaxf(v, 0.f);
                C[(size_t)m2*N+n] = v;
            }
        }
    }
}

// ---------------- persistent GRU (tensor GEMM, B-frags reg-cached) -----------
#define GRU_SMEM (53384*4)

template<int LAYER>
__global__ __launch_bounds__(256) void gru_persist(
    const __nv_bfloat16* __restrict__ GIsrc,
    const int*   __restrict__ gnf,
    const float* __restrict__ whh, const float* __restrict__ bhh,
    const float* __restrict__ h0,
    __nv_bfloat16* __restrict__ Yb, float* __restrict__ Yf)
{
    extern __shared__ float sm[];
    uint32_t* sWt  = (uint32_t*)sm;            // [320][108]
    uint32_t* sHta = (uint32_t*)(sm + 34560);  // [32][108]
    float* sG  = sm + 38016;                   // [32][332]
    float* sHT = sm + 48640;                   // [100][34]
    float* sB  = sm + 52040;                   // [320]
    int*  sTok = (int*)(sm + 52360);           // [1024]
    int tid = threadIdx.x;
    int w = tid >> 5, lane = tid & 31;
    int g = lane >> 2, t = lane & 3;
    int w5 = w * 5;
    int rowbase = blockIdx.x * 32;

    for (int idx = tid; idx < 320 * 108; idx += 256) {
        int col = idx / 108, k = idx - col * 108;
        float v = (col < 300 && k < 100) ? whh[col * 100 + k] : 0.f;
        sWt[idx] = totf32(v);
    }
    for (int idx = tid; idx < 32 * 108; idx += 256) {
        int r = idx / 108, k = idx - r * 108;
        float v = (k < 100) ? h0[(size_t)(rowbase + r) * 100 + k] : 0.f;
        sHta[idx] = totf32(v);
    }
    for (int idx = tid; idx < 3200; idx += 256) {
        int r = idx / 100, c = idx - r * 100;
        sHT[c*34 + r] = h0[(size_t)(rowbase + r)*100 + c];
    }
    for (int idx = tid; idx < 320; idx += 256) sB[idx] = (idx < 300) ? bhh[idx] : 0.f;
    if (LAYER == 0) {
        for (int idx = tid; idx < 1024; idx += 256)
            sTok[idx] = gnf[rowbase * SEQL + idx];
    }
    __syncthreads();

    // cache B fragments for n-tiles j=0..2 in registers (step-invariant)
    uint32_t breg[3][13][2];
    #pragma unroll
    for (int j = 0; j < 3; j++) {
        int cb = (w5 + j) * 8 + g;
        #pragma unroll
        for (int ks = 0; ks < 13; ks++) {
            breg[j][ks][0] = sWt[cb * 108 + ks * 8 + t];
            breg[j][ks][1] = sWt[cb * 108 + ks * 8 + t + 4];
        }
    }

    int pr[13], pc[13];
    #pragma unroll
    for (int q = 0; q < 13; q++) {
        int cell = tid + q * 256;
        pr[q] = cell / 100;
        pc[q] = cell - pr[q] * 100;
    }

    for (int s = 0; s < SEQL; s++) {
        float pg[13][3];
        #pragma unroll
        for (int q = 0; q < 13; q++) {
            int cell = tid + q * 256;
            if (cell < 3200) {
                int r = pr[q], c = pc[q];
                const __nv_bfloat16* gi;
                if (LAYER == 0) {
                    int tok = sTok[r * SEQL + s];
                    gi = GIsrc + (size_t)tok * 300;
                } else {
                    gi = GIsrc + ((size_t)s * NTW + (rowbase + r)) * 300;
                }
                pg[q][0] = __bfloat162float(gi[c]);
                pg[q][1] = __bfloat162float(gi[c + 100]);
                pg[q][2] = __bfloat162float(gi[c + 200]);
            }
        }

        float dfr[2][5][4];
        #pragma unroll
        for (int i = 0; i < 2; i++)
            #pragma unroll
            for (int j = 0; j < 5; j++)
                #pragma unroll
                for (int q = 0; q < 4; q++) dfr[i][j][q] = 0.f;

        #pragma unroll
        for (int ks = 0; ks < 13; ks++) {
            int k0 = ks * 8;
            uint32_t a[2][4];
            #pragma unroll
            for (int i = 0; i < 2; i++) {
                int r = i * 16 + g;
                a[i][0] = sHta[r * 108 + k0 + t];
                a[i][1] = sHta[(r + 8) * 108 + k0 + t];
                a[i][2] = sHta[r * 108 + k0 + t + 4];
                a[i][3] = sHta[(r + 8) * 108 + k0 + t + 4];
            }
            #pragma unroll
            for (int j = 0; j < 3; j++) {
                mma_tf32(dfr[0][j], a[0], breg[j][ks][0], breg[j][ks][1]);
                mma_tf32(dfr[1][j], a[1], breg[j][ks][0], breg[j][ks][1]);
            }
            #pragma unroll
            for (int j = 3; j < 5; j++) {
                int cb = (w5 + j) * 8 + g;
                uint32_t b0 = sWt[cb * 108 + k0 + t];
                uint32_t b1 = sWt[cb * 108 + k0 + t + 4];
                mma_tf32(dfr[0][j], a[0], b0, b1);
                mma_tf32(dfr[1][j], a[1], b0, b1);
            }
        }
        #pragma unroll
        for (int i = 0; i < 2; i++) {
            int r1 = i * 16 + g, r2 = r1 + 8;
            #pragma unroll
            for (int j = 0; j < 5; j++) {
                int col = (w5 + j) * 8 + 2 * t;
                sG[r1 * 332 + col]     = dfr[i][j][0];
                sG[r1 * 332 + col + 1] = dfr[i][j][1];
                sG[r2 * 332 + col]     = dfr[i][j][2];
                sG[r2 * 332 + col + 1] = dfr[i][j][3];
            }
        }
        __syncthreads();

        #pragma unroll
        for (int q = 0; q < 13; q++) {
            int cell = tid + q * 256;
            if (cell < 3200) {
                int r = pr[q], c = pc[q];
                float hr  = sG[r*332 + c]       + sB[c];
                float hz  = sG[r*332 + c + 100] + sB[c+100];
                float hnn = sG[r*332 + c + 200] + sB[c+200];
                float h   = sHT[c*34 + r];
                float rg = sigmoid_ffma(pg[q][0] + hr);
                float zg = __fdividef(1.f, 1.f + __expf(-(pg[q][1] + hz)));
                float x  = pg[q][2] + rg * hnn;
                float tt = __expf(-2.f * fabsf(x));
                float ng = copysignf(__fdividef(1.f - tt, 1.f + tt), x);
                float hn = (1.f - zg) * ng + zg * h;
                sHT[c*34 + r] = hn;
                sHta[r*108 + c] = totf32(hn);
                if (LAYER == 0)
                    Yb[((size_t)s * NTW + (rowbase + r)) * 100 + c] =
                        __float2bfloat16_rn(hn);
            }
        }
        __syncthreads();
    }
    if (LAYER == 1) {
        for (int ii = tid; ii < 3200; ii += 256) {
            int r = ii / 100, c = ii - r * 100;
            int grow = rowbase + r;
            int orow = (grow < BSZ) ? grow : grow + NUSR;
            Yf[(size_t)orow * 100 + c] = sHT[c*34 + r];
        }
    }
}

// ---------------- graph structure kernels ------------------------------------
__global__ void k_zero3(double* accP, double* accW, double* accK) {
    int i = threadIdx.x;
    if (i < 96) { accP[i] = 0.0; accW[i] = 0.0; }
    if (i < 64) accK[i] = 0.0;
}
__global__ void k_cat(const float* __restrict__ cmw, const float* __restrict__ clw,
                      float* __restrict__ wcat) {
    int i = blockIdx.x * 256 + threadIdx.x;
    if (i >= 64 * 200) return;
    int k = i / 200, c = i - k * 200;
    wcat[i] = (c < 100) ? cmw[k * 100 + c] : clw[k * 100 + (c - 100)];
}
__global__ void k_scatter_cnt(const int* __restrict__ src, const int* __restrict__ dst,
                              unsigned* __restrict__ cnt, unsigned* __restrict__ cntT,
                              int* __restrict__ deg) {
    int e = blockIdx.x * 256 + threadIdx.x;
    if (e >= NEDGE) return;
    int s = src[e], d = dst[e];
    size_t idx  = (size_t)s * NN + d;
    size_t idxT = (size_t)d * NN + s;
    atomicAdd(&cnt [idx  >> 2], 1u << ((idx  & 3) * 8));
    atomicAdd(&cntT[idxT >> 2], 1u << ((idxT & 3) * 8));
    atomicAdd(&deg[d], 1);
}
__global__ __launch_bounds__(1024) void k_prefix(const int* __restrict__ cnt,
                                                 int* __restrict__ rowptr,
                                                 int* __restrict__ fill,
                                                 float* __restrict__ dis) {
    __shared__ int part[1024];
    int tid = threadIdx.x;
    int base = tid * 6;
    int loc[6], cv[6];
    int s = 0;
    #pragma unroll
    for (int i = 0; i < 6; i++) { cv[i] = cnt[base + i]; loc[i] = s; s += cv[i]; }
    part[tid] = s;
    __syncthreads();
    for (int o = 1; o < 1024; o <<= 1) {
        int t = (tid >= o) ? part[tid - o] : 0;
        __syncthreads();
        part[tid] += t;
        __syncthreads();
    }
    int excl = part[tid] - s;
    #pragma unroll
    for (int i = 0; i < 6; i++) {
        rowptr[base + i] = excl + loc[i];
        fill[base + i] = 0;
        dis[base + i] = rsqrtf((float)cv[i] + 1.f);
    }
    if (tid == 1023) rowptr[NN] = part[1023];
}
__global__ void k_fill(const int* __restrict__ src, const int* __restrict__ dst,
                       const int* __restrict__ rowptr, int* __restrict__ fill,
                       const float* __restrict__ dis,
                       int* __restrict__ esrc, float* __restrict__ ecoef) {
    int e = blockIdx.x * 256 + threadIdx.x;
    if (e >= NEDGE) return;
    int s = src[e], d = dst[e];
    int pos = rowptr[d] + atomicAdd(&fill[d], 1);
    esrc[pos] = s;
    ecoef[pos] = dis[s] * dis[d];
}

// ---------------- CSR aggregation kernels -------------------------------------
__global__ __launch_bounds__(256) void k_agg1(
    const float* __restrict__ xw, const float* __restrict__ b,
    const int* __restrict__ rowptr, const int* __restrict__ esrc,
    const float* __restrict__ ecoef, const float* __restrict__ dis,
    float* __restrict__ outv)
{
    int task = blockIdx.x * 8 + (threadIdx.x >> 5);
    int lane = threadIdx.x & 31;
    int n = task >> 1;
    int c = ((task & 1) << 5) + lane;
    if (n >= NN) return;
    float dn = dis[n];
    float v = xw[(size_t)n*64 + c] * dn * dn + b[c];
    int p1 = rowptr[n+1];
    for (int p = rowptr[n]; p < p1; p++) {
        int s = esrc[p];
        v = fmaf(xw[(size_t)s*64 + c], ecoef[p], v);
    }
    outv[(size_t)n*64 + c] = (v > 0.f) ? v : expm1f(v);
}
__global__ __launch_bounds__(256) void k_aggmulv(
    const float* __restrict__ xwc,
    const float* __restrict__ bm, const float* __restrict__ bl,
    const int* __restrict__ rowptr, const int* __restrict__ esrc,
    const float* __restrict__ ecoef, const float* __restrict__ dis,
    const float* __restrict__ eps, float* __restrict__ Z,
    float* __restrict__ out, double* __restrict__ accK)
{
    __shared__ float wred[8];
    int task = blockIdx.x * 8 + (threadIdx.x >> 5);
    int lane = threadIdx.x & 31;
    int n = task >> 2;
    int c = ((task & 3) << 5) + lane;
    float kl = 0.f;
    if (n < NN && c < 100) {
        float dn = dis[n];
        float d2 = dn * dn;
        float vm = fmaf(xwc[(size_t)n*200 + c],       d2, bm[c]);
        float vl = fmaf(xwc[(size_t)n*200 + 100 + c], d2, bl[c]);
        int p1 = rowptr[n+1];
        for (int p = rowptr[n]; p < p1; p++) {
            int s = esrc[p];
            float co = ecoef[p];
            vm = fmaf(xwc[(size_t)s*200 + c],       co, vm);
            vl = fmaf(xwc[(size_t)s*200 + 100 + c], co, vl);
        }
        float mu = fmaxf(vm, 0.f);
        float lv = fmaxf(vl, 0.f);
        float z = fmaf(expf(lv * 0.5f), eps[(size_t)n*100 + c], mu);
        Z[(size_t)n*100 + c] = z;
        if (n < BSZ) out[(size_t)n*100 + c] = z;
        kl = -0.5f * (1.f + lv - mu*mu - expf(lv));
    }
    #pragma unroll
    for (int o = 16; o > 0; o >>= 1)
        kl += __shfl_down_sync(0xFFFFFFFFu, kl, o);
    if (lane == 0) wred[threadIdx.x >> 5] = kl;
    __syncthreads();
    if (threadIdx.x == 0) {
        float t = 0.f;
        #pragma unroll
        for (int w = 0; w < 8; w++) t += wred[w];
        atomicAdd(&accK[blockIdx.x & 63], (double)t);
    }
}

// ---------------- Z@Z^T loss -------------------------------------------------
#define ZZT_SMEM (2*64*108*4)
__global__ __launch_bounds__(256) void k_zzt7(const float* __restrict__ Z,
                                              const unsigned* __restrict__ cnt,
                                              const unsigned* __restrict__ cntT,
                                              double* __restrict__ accP,
                                              double* __restrict__ accW) {
    int q = blockIdx.x;
    int bjB = (int)((sqrt(8.0 * q + 1.0) - 1.0) * 0.5);
    while ((bjB + 1) * (bjB + 2) / 2 <= q) bjB++;
    while (bjB * (bjB + 1) / 2 > q) bjB--;
    int biB = q - bjB * (bjB + 1) / 2;

    extern __shared__ uint32_t zsm[];
    uint32_t* zA = zsm;
    uint32_t* zB = zsm + 64*108;
    int tid = threadIdx.x;
    int w = tid >> 5, lane = tid & 31;
    int g = lane >> 2, t = lane & 3;
    int bi = biB * 64, bj = bjB * 64;

    for (int f = tid; f < 64 * 104; f += 256) {
        int r = f / 104, k = f - r * 104;
        float va = (k < 100) ? Z[(size_t)(bi + r) * 100 + k] : 0.f;
        float vb = (k < 100) ? Z[(size_t)(bj + r) * 100 + k] : 0.f;
        zA[r * 108 + k] = totf32(va);
        zB[r * 108 + k] = totf32(vb);
    }
    __syncthreads();

    int mg = (w & 1) * 32;
    int ngrp = (w >> 1) * 16;

    float d[2][2][4];
    #pragma unroll
    for (int i = 0; i < 2; i++)
        #pragma unroll
        for (int j = 0; j < 2; j++)
            #pragma unroll
            for (int e = 0; e < 4; e++) d[i][j][e] = 0.f;

    #pragma unroll
    for (int ks = 0; ks < 13; ks++) {
        int k0 = ks * 8;
        uint32_t a[2][4];
        #pragma unroll
        for (int i = 0; i < 2; i++) {
            int r = mg + i * 16 + g;
            a[i][0] = zA[r * 108 + k0 + t];
            a[i][1] = zA[(r + 8) * 108 + k0 + t];
            a[i][2] = zA[r * 108 + k0 + t + 4];
            a[i][3] = zA[(r + 8) * 108 + k0 + t + 4];
        }
        #pragma unroll
        for (int j = 0; j < 2; j++) {
            int cb = ngrp + j * 8 + g;
            uint32_t b0 = zB[cb * 108 + k0 + t];
            uint32_t b1 = zB[cb * 108 + k0 + t + 4];
            mma_tf32(d[0][j], a[0], b0, b1);
            mma_tf32(d[1][j], a[1], b0, b1);
        }
    }

    bool diag = (biB == bjB);
    float sp = 0.f, sw = 0.f;
    #pragma unroll
    for (int i = 0; i < 2; i++) {
        #pragma unroll
        for (int half = 0; half < 2; half++) {
            int iloc = mg + i * 16 + g + half * 8;
            int ig = bi + iloc;
            #pragma unroll
            for (int j = 0; j < 2; j++) {
                int cloc = ngrp + j * 8 + 2 * t;
                int jg = bj + cloc;
                unsigned wrow  = cnt [(size_t)ig * (NN/4) + ((unsigned)jg >> 2)];
                unsigned wrowT = diag ? 0u
                               : cntT[(size_t)ig * (NN/4) + ((unsigned)jg >> 2)];
                #pragma unroll
                for (int e = 0; e < 2; e++) {
                    float zv = d[i][j][half * 2 + e];
                    int col = jg + e;
                    float u = __expf(-fabsf(zv));
                    float r = recip1p(u);
                    float s = (zv >= 0.f) ? r : u * r;
                    float lg = __logf(1.f + u);
                    float mlogp, mlog1mp;
                    if (zv > 15.942384f) {
                        mlogp = 1.1920929e-7f; mlog1mp = 15.9423847f;
                    } else if (zv < -16.118095f) {
                        mlogp = 16.118095f;    mlog1mp = 1.0000000e-7f;
                    } else {
                        mlogp = (zv >= 0.f) ? lg : (lg - zv);
                        mlog1mp = zv + mlogp;
                    }
                    float ag1 = (float)((wrow >> ((col & 3) * 8)) & 0xFFu)
                              + ((ig == col) ? 1.f : 0.f);
                    float wg1 = (ag1 == 1.f) ? PWc : 1.f;
                    sp += s;
                    sw += wg1 * (ag1 * mlogp + (1.f - ag1) * mlog1mp);
                    if (!diag) {
                        float ag2 = (float)((wrowT >> ((col & 3) * 8)) & 0xFFu);
                        float wg2 = (ag2 == 1.f) ? PWc : 1.f;
                        sp += s;
                        sw += wg2 * (ag2 * mlogp + (1.f - ag2) * mlog1mp);
                    }
                }
            }
        }
    }
    __syncthreads();
    double* red = (double*)zsm;
    red[tid] = (double)sp; __syncthreads();
    for (int o = 128; o > 0; o >>= 1) {
        if (tid < o) red[tid] += red[tid + o];
        __syncthreads();
    }
    if (tid == 0) atomicAdd(&accP[bjB], red[0]);
    __syncthreads();
    red[tid] = (double)sw; __syncthreads();
    for (int o = 128; o > 0; o >>= 1) {
        if (tid < o) red[tid] += red[tid + o];
        __syncthreads();
    }
    if (tid == 0) atomicAdd(&accW[bjB], red[0]);
}

__global__ void k_fin(const double* __restrict__ accP, const double* __restrict__ accW,
                      const double* __restrict__ accK, float* __restrict__ out) {
    double sp = 0.0, sw = 0.0, sk = 0.0;
    for (int i = 0; i < 96; i++) { sp += accP[i]; sw += accW[i]; }
    for (int i = 0; i < 64; i++) sk += accK[i];
    double norm = N2D / ((N2D - sp) * 2.0);
    out[BSZ * 100]     = (float)(sk / (double)NN);
    out[BSZ * 100 + 1] = (float)(norm * (sw / N2D));
}

// ---------------- host launch ------------------------------------------------
extern "C" void kernel_launch(void* const* d_in, const int* in_sizes, int n_in,
                              void* d_out, int out_size) {
    const float* user_feats = (const float*)d_in[0];
    const int*   gnf        = (const int*)  d_in[1];
    const int*   eidx       = (const int*)  d_in[2];
    const float* h0         = (const float*)d_in[4];
    const float* eps        = (const float*)d_in[5];
    const float* emb        = (const float*)d_in[6];
    const float* mw1 = (const float*)d_in[7],  *mb1 = (const float*)d_in[8];
    const float* mw2 = (const float*)d_in[9],  *mb2 = (const float*)d_in[10];
    const float* wih0 = (const float*)d_in[11], *whh0 = (const float*)d_in[12];
    const float* bih0 = (const float*)d_in[13], *bhh0 = (const float*)d_in[14];
    const float* wih1 = (const float*)d_in[15], *whh1 = (const float*)d_in[16];
    const float* bih1 = (const float*)d_in[17], *bhh1 = (const float*)d_in[18];
    const float* c1w = (const float*)d_in[19], *c1b = (const float*)d_in[20];
    const float* cmw = (const float*)d_in[21], *cmb = (const float*)d_in[22];
    const float* clw = (const float*)d_in[23], *clb = (const float*)d_in[24];
    float* out = (float*)d_out;
    const int* srcp = eidx;
    const int* dstp = eidx + NEDGE;

    void* p;
    cudaGetSymbolAddress(&p, g_Gi);  __nv_bfloat16* GiB = (__nv_bfloat16*)p;
    cudaGetSymbolAddress(&p, g_Y0);  __nv_bfloat16* Y0B = (__nv_bfloat16*)p;
    cudaGetSymbolAddress(&p, g_T1);  float* T1  = (float*)p;
    cudaGetSymbolAddress(&p, g_Xin); float* Xin = (float*)p;
    cudaGetSymbolAddress(&p, g_XW);  float* XW1 = (float*)p;
    cudaGetSymbolAddress(&p, g_XWc); float* XWc = (float*)p;
    cudaGetSymbolAddress(&p, g_Wcat); float* Wcat = (float*)p;
    cudaGetSymbolAddress(&p, g_Hc);  float* Hc  = (float*)p;
    cudaGetSymbolAddress(&p, g_Z);   float* Z   = (float*)p;
    cudaGetSymbolAddress(&p, g_dis); float* dis = (float*)p;
    cudaGetSymbolAddress(&p, g_cnt);    int* cntI = (int*)p;
    cudaGetSymbolAddress(&p, g_rowptr); int* rowptr = (int*)p;
    cudaGetSymbolAddress(&p, g_fill);   int* fill = (int*)p;
    cudaGetSymbolAddress(&p, g_esrc);   int* esrc = (int*)p;
    cudaGetSymbolAddress(&p, g_ecoef);  float* ecoef = (float*)p;
    cudaGetSymbolAddress(&p, g_Acnt);   unsigned* Acnt = (unsigned*)p;
    cudaGetSymbolAddress(&p, g_AcntT);  unsigned* AcntT = (unsigned*)p;
    cudaGetSymbolAddress(&p, g_accP);   double* accP = (double*)p;
    cudaGetSymbolAddress(&p, g_accW);   double* accW = (double*)p;
    cudaGetSymbolAddress(&p, g_accK);   double* accK = (double*)p;

    static bool inited = false;
    static cudaStream_t s2;
    static cudaEvent_t evRoot, evSetup;
    if (!inited) {
        cudaStreamCreateWithFlags(&s2, cudaStreamNonBlocking);
        cudaEventCreateWithFlags(&evRoot,  cudaEventDisableTiming);
        cudaEventCreateWithFlags(&evSetup, cudaEventDisableTiming);
        cudaFuncSetAttribute(gru_persist<0>, cudaFuncAttributeMaxDynamicSharedMemorySize, GRU_SMEM);
        cudaFuncSetAttribute(gru_persist<1>, cudaFuncAttributeMaxDynamicSharedMemorySize, GRU_SMEM);
        cudaFuncSetAttribute(k_zzt7, cudaFuncAttributeMaxDynamicSharedMemorySize, ZZT_SMEM);
        cudaFuncSetAttribute(wgemm_tf32<0>, cudaFuncAttributeMaxDynamicSharedMemorySize, WG_SMEM);
        cudaFuncSetAttribute(wgemm_tf32<1>, cudaFuncAttributeMaxDynamicSharedMemorySize, WG_SMEM);
        inited = true;
    }

    cudaEventRecord(evRoot, 0);

    // ---- side stream s2: graph setup + user MLP + weight concat ----
    cudaStreamWaitEvent(s2, evRoot, 0);
    cudaMemsetAsync(Acnt,  0, (size_t)NN * (NN/4) * sizeof(unsigned), s2);
    cudaMemsetAsync(AcntT, 0, (size_t)NN * (NN/4) * sizeof(unsigned), s2);
    cudaMemsetAsync(cntI, 0, NN * sizeof(int), s2);
    k_zero3<<<1, 128, 0, s2>>>(accP, accW, accK);
    k_cat<<<50, 256, 0, s2>>>(cmw, clw, Wcat);
    k_scatter_cnt<<<(NEDGE + 255)/256, 256, 0, s2>>>(srcp, dstp, Acnt, AcntT, cntI);
    k_prefix<<<1, 1024, 0, s2>>>(cntI, rowptr, fill, dis);
    k_fill<<<(NEDGE + 255)/256, 256, 0, s2>>>(srcp, dstp, rowptr, fill, dis, esrc, ecoef);
    sgemm4<0,7><<<dim3(1, 16), 256, 0, s2>>>(user_feats, mw1, mb1, T1, NUSR, 100, 9, 1, 0);
    sgemm4<0,7><<<dim3(1, 16), 256, 0, s2>>>(T1, mw2, mb2, Xin + (size_t)BSZ*100, NUSR, 100, 100, 0, 0);
    cudaEventRecord(evSetup, s2);

    // ---- main: E2G (warp-MMA tf32 -> bf16) ----
    wgemm_tf32<0><<<(VOCAB + 127)/128, 256, WG_SMEM>>>(emb, wih0, bih0, GiB, VOCAB, 300, 10);

    gru_persist<0><<<128, 256, GRU_SMEM>>>(GiB, gnf, whh0, bhh0, h0, Y0B, nullptr);

    // ---- Gi1 (warp-MMA tf32, bf16 A -> bf16 out) ----
    wgemm_tf32<1><<<RALL/128, 256, WG_SMEM>>>(Y0B, wih1, bih1, GiB, RALL, 100, 4);

    gru_persist<1><<<128, 256, GRU_SMEM>>>(GiB, nullptr, whh1, bhh1,
                                           h0 + (size_t)NTW*HID, nullptr, Xin);

    // join setup (CSR + UE rows of Xin + Wcat) before convs
    cudaStreamWaitEvent(0, evSetup, 0);

    // conv1 -> elu
    sgemm4<0,4><<<dim3(1, 48), 256>>>(Xin, c1w, nullptr, XW1, NN, 64, 100, 0, 0);
    k_agg1<<<NN*2/8, 256>>>(XW1, c1b, rowptr, esrc, ecoef, dis, Hc);

    // convmu + convlv in one GEMM (N=200 concat)
    sgemm4<0,13><<<dim3(1, 48), 256>>>(Hc, Wcat, nullptr, XWc, NN, 200, 64, 0, 0);

    k_aggmulv<<<NN*4/8, 256>>>(XWc, cmb, clb, rowptr, esrc, ecoef, dis,
                               eps, Z, out, accK);

    k_zzt7<<<96*97/2, 256, ZZT_SMEM>>>(Z, Acnt, AcntT, accP, accW);
    k_fin<<<1, 1>>>(accP, accW, accK, out);
}